// round 1
// baseline (speedup 1.0000x reference)
#include <cuda_runtime.h>
#include <math.h>

// ---------------------------------------------------------------------------
// Causal FFT convolution matching:
//   X = rfft(x, n=163839); H = rfft(h, n=163839); Y = X*H
//   y = irfft(Y)            (default n = 2*(81920-1) = 163838  <-- grid mismatch!)
//   out = y[..., :131072]
// Implemented via Bluestein chirp-z transforms on a 2^18 complex FFT
// (four-step 512x512, shared-memory radix-8 FFT-512, scrambled-order safe
//  because spectra only meet in pointwise multiplies with identically
//  transformed chirp kernels).
// ---------------------------------------------------------------------------

#define M_FFT  262144      // 2^18 convolution FFT size
#define NPAIR  128         // 32*4 independent (batch, channel) signals
#define LX     131072      // x length (= 2^17)
#define LH     32768       // h length
#define KBINS  81920       // number of rfft bins of N1
#define N1C    163839      // analysis length (odd)
#define N2C    163838      // synthesis length (even)
#define SD     520         // shared tile row stride (512 + pad)

// ------------------------- static device scratch ---------------------------
__device__ float2 g_bufA[(size_t)NPAIR * M_FFT];   // 268 MB
__device__ float2 g_bufB[(size_t)NPAIR * M_FFT];   // 268 MB
__device__ float2 g_HS [(size_t)NPAIR * KBINS];    // 84 MB : H[k] spectra
__device__ float2 g_T1 [LX];                        // chirp exp(-i pi n^2 / N1)
__device__ float2 g_T2 [LX];                        // chirp exp(+i pi n^2 / N2)
__device__ float2 g_W512[512];                      // exp(-2pi i j/512)
__device__ float2 g_WN [512];                       // exp(-2pi i j/2^18)
__device__ float2 g_kern [2 * M_FFT];               // chirp kernels b1, b2
__device__ float2 g_kspec[2 * M_FFT];               // their FFTs

// ------------------------- complex helpers ---------------------------------
__device__ __forceinline__ float2 cadd(float2 a, float2 b){ return make_float2(a.x+b.x, a.y+b.y); }
__device__ __forceinline__ float2 csub(float2 a, float2 b){ return make_float2(a.x-b.x, a.y-b.y); }
__device__ __forceinline__ float2 cmul(float2 a, float2 b){
    return make_float2(a.x*b.x - a.y*b.y, a.x*b.y + a.y*b.x);
}
template<int SIGN> __device__ __forceinline__ float2 mul_i(float2 a){
    // multiply by SIGN*i  (forward FFT uses SIGN=-1 -> multiply by -i)
    return (SIGN < 0) ? make_float2(a.y, -a.x) : make_float2(-a.y, a.x);
}

template<int SIGN>
__device__ __forceinline__ void fft4(float2 &x0, float2 &x1, float2 &x2, float2 &x3){
    float2 t0 = cadd(x0, x2), t1 = csub(x0, x2);
    float2 t2 = cadd(x1, x3), t3 = csub(x1, x3);
    float2 t3r = mul_i<SIGN>(t3);
    x0 = cadd(t0, t2);
    x2 = csub(t0, t2);
    x1 = cadd(t1, t3r);
    x3 = csub(t1, t3r);
}

template<int SIGN>
__device__ __forceinline__ void fft8(float2 u[8]){
    float2 e0=u[0], e1=u[2], e2=u[4], e3=u[6];
    float2 o0=u[1], o1=u[3], o2=u[5], o3=u[7];
    fft4<SIGN>(e0,e1,e2,e3);
    fft4<SIGN>(o0,o1,o2,o3);
    const float s2 = 0.70710678118654752440f;
    float2 w1 = make_float2( s2, SIGN * s2);
    float2 w3 = make_float2(-s2, SIGN * s2);
    o1 = cmul(o1, w1);
    o2 = mul_i<SIGN>(o2);
    o3 = cmul(o3, w3);
    u[0]=cadd(e0,o0); u[4]=csub(e0,o0);
    u[1]=cadd(e1,o1); u[5]=csub(e1,o1);
    u[2]=cadd(e2,o2); u[6]=csub(e2,o2);
    u[3]=cadd(e3,o3); u[7]=csub(e3,o3);
}

// Natural-order in/out FFT-512. 8 FFTs per block: fft id = tid>>6, lane = tid&63.
// Caller must __syncthreads() after filling shared before calling.
template<int SIGN>
__device__ void fft512_block(float2* s, const float2* shW, int tid){
    int f = tid >> 6;
    int l = tid & 63;
    float2* sp = s + f * SD;
    float2 u[8];

    // stage 0 (m=8): read input with octal digit-reversal, radix-8 butterfly
    {
        int g = l;
        #pragma unroll
        for (int q = 0; q < 8; q++){
            int src = q*64 + (g & 7)*8 + (g >> 3);   // drev(g*8+q)
            u[q] = sp[src];
        }
        fft8<SIGN>(u);
        __syncthreads();                              // all reads done
        #pragma unroll
        for (int r = 0; r < 8; r++) sp[g*8 + r] = u[r];
    }
    __syncthreads();

    // stage 1 (m=64, L=8)
    {
        int gg = l >> 3, j = l & 7;
        int base = gg*64 + j;
        #pragma unroll
        for (int q = 0; q < 8; q++) u[q] = sp[base + q*8];
        #pragma unroll
        for (int q = 1; q < 8; q++){
            float2 w = shW[q*j*8];
            if (SIGN > 0) w.y = -w.y;
            u[q] = cmul(u[q], w);
        }
        fft8<SIGN>(u);
        #pragma unroll
        for (int r = 0; r < 8; r++) sp[base + r*8] = u[r];
    }
    __syncthreads();

    // stage 2 (m=512, L=64)
    {
        int j = l;
        #pragma unroll
        for (int q = 0; q < 8; q++) u[q] = sp[j + q*64];
        #pragma unroll
        for (int q = 1; q < 8; q++){
            float2 w = shW[q*j];
            if (SIGN > 0) w.y = -w.y;
            u[q] = cmul(u[q], w);
        }
        fft8<SIGN>(u);
        #pragma unroll
        for (int r = 0; r < 8; r++) sp[j + r*64] = u[r];
    }
    __syncthreads();
}

// ------------------------- table / kernel construction ---------------------
__global__ void init_tables(){
    int i = blockIdx.x * blockDim.x + threadIdx.x;
    if (i < LX){
        unsigned long long ii = (unsigned long long)i * (unsigned long long)i;
        double s, c;
        double a1 = (double)(ii % (2ULL * N1C)) / (double)N1C;   // exp(-i pi a1)
        sincospi(a1, &s, &c);
        g_T1[i] = make_float2((float)c, (float)(-s));
        double a2 = (double)(ii % (2ULL * N2C)) / (double)N2C;   // exp(+i pi a2)
        sincospi(a2, &s, &c);
        g_T2[i] = make_float2((float)c, (float)s);
    }
    if (i < 512){
        double s, c;
        sincospi((double)i / 256.0, &s, &c);       // exp(-2pi i i/512)
        g_W512[i] = make_float2((float)c, (float)(-s));
        sincospi((double)i / 131072.0, &s, &c);    // exp(-2pi i i/2^18)
        g_WN[i]   = make_float2((float)c, (float)(-s));
    }
}

__global__ void build_kern(){
    int i = blockIdx.x * blockDim.x + threadIdx.x;
    if (i >= M_FFT) return;
    // b1[j] = conj(T1[|j|]) for j in [-(LX-1), KBINS-1], wrapped mod M
    float2 v = make_float2(0.f, 0.f);
    if (i <= KBINS - 1)               { float2 t = g_T1[i];          v = make_float2(t.x, -t.y); }
    else if (i >= M_FFT - (LX - 1))   { float2 t = g_T1[M_FFT - i];  v = make_float2(t.x, -t.y); }
    g_kern[i] = v;
    // b2[j] = conj(T2[|j|]) for j in [-(KBINS-1), LX-1], wrapped mod M
    float2 w = make_float2(0.f, 0.f);
    if (i <= LX - 1)                  { float2 t = g_T2[i];          w = make_float2(t.x, -t.y); }
    else if (i >= M_FFT - (KBINS-1))  { float2 t = g_T2[M_FFT - i];  w = make_float2(t.x, -t.y); }
    g_kern[M_FFT + i] = w;
}

// ------------------------- four-step FFT passes -----------------------------
// Layout: signal of M=2^18 viewed as [r=0..511][c=0..511], linear = r*512 + c.
// passA: FFT over r (columns) + four-step twiddle. passB: FFT over c (rows).
// Forward: passA(in->out), then passB in-place. Inverse: passB in-place (conj,
// 1/512), then passA inverse (conj pre-twiddle, conj FFT, 1/512, out-of-place).

template<int SIGN>
__global__ void __launch_bounds__(512) passA_kernel(const float2* __restrict__ in,
                                                    float2* __restrict__ out){
    __shared__ float2 sh[8 * SD];
    __shared__ float2 shW[512];
    __shared__ float2 shWN[512];
    int tid = threadIdx.x;
    size_t base = (size_t)blockIdx.y * M_FFT;
    int c0 = blockIdx.x * 8;
    if (tid < 512){ shW[tid] = g_W512[tid]; shWN[tid] = g_WN[tid]; }

    const float2* gin = in + base;
    #pragma unroll
    for (int it = 0; it < 8; it++){
        int i = it*512 + tid;
        int r = i >> 3, cc = i & 7;
        sh[cc*SD + r] = gin[r*512 + c0 + cc];
    }
    __syncthreads();

    if (SIGN > 0){
        // inverse: pre-multiply by conj four-step twiddle exp(+2pi i r*c / M)
        #pragma unroll
        for (int it = 0; it < 8; it++){
            int i = it*512 + tid;
            int r = i >> 3, cc = i & 7;
            int t = r * (c0 + cc);
            float2 tw = cmul(shW[t >> 9], shWN[t & 511]);
            tw.y = -tw.y;
            sh[cc*SD + r] = cmul(sh[cc*SD + r], tw);
        }
        __syncthreads();
    }

    fft512_block<SIGN>(sh, shW, tid);

    float2* gout = out + base;
    const float scale = (SIGN > 0) ? (1.0f / 512.0f) : 1.0f;
    #pragma unroll
    for (int it = 0; it < 8; it++){
        int i = it*512 + tid;
        int r = i >> 3, cc = i & 7;
        float2 v = sh[cc*SD + r];
        if (SIGN < 0){
            int t = r * (c0 + cc);
            float2 tw = cmul(shW[t >> 9], shWN[t & 511]);
            v = cmul(v, tw);
        } else {
            v.x *= scale; v.y *= scale;
        }
        gout[r*512 + c0 + cc] = v;
    }
}

template<int SIGN>
__global__ void __launch_bounds__(512) passB_kernel(float2* __restrict__ data){
    __shared__ float2 sh[8 * SD];
    __shared__ float2 shW[512];
    int tid = threadIdx.x;
    size_t base = (size_t)blockIdx.y * M_FFT + (size_t)blockIdx.x * (8 * 512);
    if (tid < 512) shW[tid] = g_W512[tid];

    float2* g = data + base;
    #pragma unroll
    for (int it = 0; it < 8; it++){
        int i = it*512 + tid;
        int rr = i >> 9, c = i & 511;
        sh[rr*SD + c] = g[i];
    }
    __syncthreads();

    fft512_block<SIGN>(sh, shW, tid);

    const float scale = (SIGN > 0) ? (1.0f / 512.0f) : 1.0f;
    #pragma unroll
    for (int it = 0; it < 8; it++){
        int i = it*512 + tid;
        int rr = i >> 9, c = i & 511;
        float2 v = sh[rr*SD + c];
        g[i] = make_float2(v.x * scale, v.y * scale);
    }
}

// ------------------------- pointwise stages --------------------------------
__global__ void build_ah(float2* __restrict__ A, const float* __restrict__ h){
    int i = blockIdx.x * blockDim.x + threadIdx.x;
    if (i >= NPAIR * M_FFT) return;
    int n = i & (M_FFT - 1);
    int p = i >> 18;
    float2 v = make_float2(0.f, 0.f);
    if (n < LH){
        float hv = h[(size_t)p * LH + n];
        float2 t = g_T1[n];
        v = make_float2(hv * t.x, hv * t.y);
    }
    A[i] = v;
}

__global__ void build_ax(float2* __restrict__ A, const float* __restrict__ x){
    int i = blockIdx.x * blockDim.x + threadIdx.x;
    if (i >= NPAIR * M_FFT) return;
    int n = i & (M_FFT - 1);
    int p = i >> 18;
    float2 v = make_float2(0.f, 0.f);
    if (n < LX){
        float xv = x[(size_t)p * LX + n];
        float2 t = g_T1[n];
        v = make_float2(xv * t.x, xv * t.y);
    }
    A[i] = v;
}

__global__ void mulK(float2* __restrict__ buf, const float2* __restrict__ kern){
    int i = blockIdx.x * blockDim.x + threadIdx.x;
    if (i >= NPAIR * M_FFT) return;
    buf[i] = cmul(buf[i], kern[i & (M_FFT - 1)]);
}

__global__ void mulK2(float2* __restrict__ buf, const float2* __restrict__ kern){
    // batch = 2 variant for the chirp-kernel FFTs
    int i = blockIdx.x * blockDim.x + threadIdx.x;
    if (i >= 2 * M_FFT) return;
    buf[i] = cmul(buf[i], kern[i]);
}

__global__ void extract_H(float2* __restrict__ HS, const float2* __restrict__ A){
    int i = blockIdx.x * blockDim.x + threadIdx.x;
    if (i >= NPAIR * KBINS) return;
    int k = i % KBINS;
    int p = i / KBINS;
    HS[i] = cmul(g_T1[k], A[(size_t)p * M_FFT + k]);
}

__global__ void build_d(float2* __restrict__ A, const float2* __restrict__ HS){
    int i = blockIdx.x * blockDim.x + threadIdx.x;
    if (i >= NPAIR * M_FFT) return;
    int k = i & (M_FFT - 1);
    int p = i >> 18;
    float2 v;
    if (k < KBINS){
        float2 Xk = cmul(g_T1[k], A[i]);
        float2 Y  = cmul(Xk, HS[(size_t)p * KBINS + k]);
        if (k == 0 || k == KBINS - 1){
            // pocketfft c2r ignores imag at DC / Nyquist; halve for the 2*Re(sum)
            Y = make_float2(0.5f * Y.x, 0.f);
        }
        v = cmul(Y, g_T2[k]);
    } else {
        v = make_float2(0.f, 0.f);
    }
    A[i] = v;
}

__global__ void write_out(float* __restrict__ out, const float2* __restrict__ A){
    int i = blockIdx.x * blockDim.x + threadIdx.x;
    if (i >= NPAIR * LX) return;
    int t = i & (LX - 1);
    int p = i >> 17;
    float2 S = A[(size_t)p * M_FFT + t];
    float2 T = g_T2[t];
    out[i] = (2.0f / (float)N2C) * (T.x * S.x - T.y * S.y);
}

// ------------------------- launch -------------------------------------------
extern "C" void kernel_launch(void* const* d_in, const int* in_sizes, int n_in,
                              void* d_out, int out_size){
    (void)in_sizes; (void)n_in; (void)out_size;
    const float* x = (const float*)d_in[0];
    const float* h = (const float*)d_in[1];
    float* out = (float*)d_out;

    float2 *bufA, *bufB, *hs, *kern, *kspec;
    cudaGetSymbolAddress((void**)&bufA, g_bufA);
    cudaGetSymbolAddress((void**)&bufB, g_bufB);
    cudaGetSymbolAddress((void**)&hs,   g_HS);
    cudaGetSymbolAddress((void**)&kern, g_kern);
    cudaGetSymbolAddress((void**)&kspec,g_kspec);

    const int PW  = (NPAIR * M_FFT) / 256;   // 131072 blocks
    const dim3 fgrid(64, NPAIR);
    const dim3 kgrid(64, 2);

    // 0. tables + chirp kernels + their spectra (recomputed every call: no caching)
    init_tables<<<512, 256>>>();
    build_kern<<<M_FFT / 256, 256>>>();
    passA_kernel<-1><<<kgrid, 512>>>(kern, kspec);
    passB_kernel<-1><<<kgrid, 512>>>(kspec);

    // 1. H path: CZT of h on the N1 grid -> g_HS
    build_ah<<<PW, 256>>>(bufA, h);
    passA_kernel<-1><<<fgrid, 512>>>(bufA, bufB);
    passB_kernel<-1><<<fgrid, 512>>>(bufB);
    mulK<<<PW, 256>>>(bufB, kspec);                   // * B1
    passB_kernel<+1><<<fgrid, 512>>>(bufB);
    passA_kernel<+1><<<fgrid, 512>>>(bufB, bufA);
    extract_H<<<(NPAIR * KBINS) / 256, 256>>>(hs, bufA);

    // 2. X path: CZT of x on the N1 grid (conv result left in bufA)
    build_ax<<<PW, 256>>>(bufA, x);
    passA_kernel<-1><<<fgrid, 512>>>(bufA, bufB);
    passB_kernel<-1><<<fgrid, 512>>>(bufB);
    mulK<<<PW, 256>>>(bufB, kspec);                   // * B1
    passB_kernel<+1><<<fgrid, 512>>>(bufB);
    passA_kernel<+1><<<fgrid, 512>>>(bufB, bufA);

    // 3. Y = X*H, halve DC/Nyquist, pre-chirp for the N2 synthesis CZT
    build_d<<<PW, 256>>>(bufA, hs);
    passA_kernel<-1><<<fgrid, 512>>>(bufA, bufB);
    passB_kernel<-1><<<fgrid, 512>>>(bufB);
    mulK<<<PW, 256>>>(bufB, kspec + M_FFT);           // * B2
    passB_kernel<+1><<<fgrid, 512>>>(bufB);
    passA_kernel<+1><<<fgrid, 512>>>(bufB, bufA);

    // 4. y[t] = (2/N2) * Re( T2[t] * conv[t] ), first LX samples
    write_out<<<(NPAIR * LX) / 256, 256>>>(out, bufA);
}

// round 3
// speedup vs baseline: 1.2309x; 1.2309x over previous
#include <cuda_runtime.h>
#include <math.h>

// ---------------------------------------------------------------------------
// Causal FFT convolution matching:
//   X = rfft(x, n=163839); H = rfft(h, n=163839); Y = X*H
//   y = irfft(Y)            (default n = 163838  <-- mismatched grids!)
//   out = y[..., :131072]
// Bluestein CZTs on a 2^18 four-step FFT (512x512), heavily fused:
//   - passB_fwd * kernel-spectrum * passB_inv fused in shared memory
//   - input chirp / H-extract / output stages fused into passA pro/epilogues
//   - CZT-X inverse passA + Y=X*H pointwise + CZT-3 forward passA fused
// R2 fix: inverse-passA prologues must sync between loading the twiddle
// tables into shared and using them (race caused NaN).
// ---------------------------------------------------------------------------

#define M_FFT  262144
#define NPAIR  128
#define LX     131072
#define LH     32768
#define KBINS  81920
#define N1C    163839
#define N2C    163838
#define SD     520

__device__ float2 g_bufA[(size_t)NPAIR * M_FFT];   // 268 MB
__device__ float2 g_HS [(size_t)NPAIR * KBINS];    // 84 MB
__device__ float2 g_T1 [LX];
__device__ float2 g_T2 [LX];
__device__ float2 g_W512[512];
__device__ float2 g_WN [512];
__device__ float2 g_kern [2 * M_FFT];
__device__ float2 g_kspec[2 * M_FFT];

// ------------------------- complex helpers ---------------------------------
__device__ __forceinline__ float2 cadd(float2 a, float2 b){ return make_float2(a.x+b.x, a.y+b.y); }
__device__ __forceinline__ float2 csub(float2 a, float2 b){ return make_float2(a.x-b.x, a.y-b.y); }
__device__ __forceinline__ float2 cmul(float2 a, float2 b){
    return make_float2(a.x*b.x - a.y*b.y, a.x*b.y + a.y*b.x);
}
template<int SIGN> __device__ __forceinline__ float2 mul_i(float2 a){
    return (SIGN < 0) ? make_float2(a.y, -a.x) : make_float2(-a.y, a.x);
}

template<int SIGN>
__device__ __forceinline__ void fft4(float2 &x0, float2 &x1, float2 &x2, float2 &x3){
    float2 t0 = cadd(x0, x2), t1 = csub(x0, x2);
    float2 t2 = cadd(x1, x3), t3 = csub(x1, x3);
    float2 t3r = mul_i<SIGN>(t3);
    x0 = cadd(t0, t2);
    x2 = csub(t0, t2);
    x1 = cadd(t1, t3r);
    x3 = csub(t1, t3r);
}

template<int SIGN>
__device__ __forceinline__ void fft8(float2 u[8]){
    float2 e0=u[0], e1=u[2], e2=u[4], e3=u[6];
    float2 o0=u[1], o1=u[3], o2=u[5], o3=u[7];
    fft4<SIGN>(e0,e1,e2,e3);
    fft4<SIGN>(o0,o1,o2,o3);
    const float s2 = 0.70710678118654752440f;
    float2 w1 = make_float2( s2, SIGN * s2);
    float2 w3 = make_float2(-s2, SIGN * s2);
    o1 = cmul(o1, w1);
    o2 = mul_i<SIGN>(o2);
    o3 = cmul(o3, w3);
    u[0]=cadd(e0,o0); u[4]=csub(e0,o0);
    u[1]=cadd(e1,o1); u[5]=csub(e1,o1);
    u[2]=cadd(e2,o2); u[6]=csub(e2,o2);
    u[3]=cadd(e3,o3); u[7]=csub(e3,o3);
}

// Natural-order in/out FFT-512 in shared memory. 8 FFTs per 512-thread block.
// Caller must __syncthreads() after filling shared (and shW) before calling.
template<int SIGN>
__device__ void fft512_block(float2* s, const float2* shW, int tid){
    int f = tid >> 6;
    int l = tid & 63;
    float2* sp = s + f * SD;
    float2 u[8];

    { // stage 0: digit-reversed gather, radix-8
        int g = l;
        #pragma unroll
        for (int q = 0; q < 8; q++){
            int src = q*64 + (g & 7)*8 + (g >> 3);
            u[q] = sp[src];
        }
        fft8<SIGN>(u);
        __syncthreads();
        #pragma unroll
        for (int r = 0; r < 8; r++) sp[g*8 + r] = u[r];
    }
    __syncthreads();

    { // stage 1 (m=64)
        int gg = l >> 3, j = l & 7;
        int base = gg*64 + j;
        #pragma unroll
        for (int q = 0; q < 8; q++) u[q] = sp[base + q*8];
        #pragma unroll
        for (int q = 1; q < 8; q++){
            float2 w = shW[q*j*8];
            if (SIGN > 0) w.y = -w.y;
            u[q] = cmul(u[q], w);
        }
        fft8<SIGN>(u);
        #pragma unroll
        for (int r = 0; r < 8; r++) sp[base + r*8] = u[r];
    }
    __syncthreads();

    { // stage 2 (m=512)
        int j = l;
        #pragma unroll
        for (int q = 0; q < 8; q++) u[q] = sp[j + q*64];
        #pragma unroll
        for (int q = 1; q < 8; q++){
            float2 w = shW[q*j];
            if (SIGN > 0) w.y = -w.y;
            u[q] = cmul(u[q], w);
        }
        fft8<SIGN>(u);
        #pragma unroll
        for (int r = 0; r < 8; r++) sp[j + r*64] = u[r];
    }
    __syncthreads();
}

// ------------------------- table / kernel construction ---------------------
__global__ void init_tables(){
    int i = blockIdx.x * blockDim.x + threadIdx.x;
    if (i < LX){
        unsigned long long ii = (unsigned long long)i * (unsigned long long)i;
        double s, c;
        double a1 = (double)(ii % (2ULL * N1C)) / (double)N1C;
        sincospi(a1, &s, &c);
        g_T1[i] = make_float2((float)c, (float)(-s));
        double a2 = (double)(ii % (2ULL * N2C)) / (double)N2C;
        sincospi(a2, &s, &c);
        g_T2[i] = make_float2((float)c, (float)s);
    }
    if (i < 512){
        double s, c;
        sincospi((double)i / 256.0, &s, &c);
        g_W512[i] = make_float2((float)c, (float)(-s));
        sincospi((double)i / 131072.0, &s, &c);
        g_WN[i]   = make_float2((float)c, (float)(-s));
    }
}

__global__ void build_kern(){
    int i = blockIdx.x * blockDim.x + threadIdx.x;
    if (i >= M_FFT) return;
    float2 v = make_float2(0.f, 0.f);
    if (i <= KBINS - 1)               { float2 t = g_T1[i];          v = make_float2(t.x, -t.y); }
    else if (i >= M_FFT - (LX - 1))   { float2 t = g_T1[M_FFT - i];  v = make_float2(t.x, -t.y); }
    g_kern[i] = v;
    float2 w = make_float2(0.f, 0.f);
    if (i <= LX - 1)                  { float2 t = g_T2[i];          w = make_float2(t.x, -t.y); }
    else if (i >= M_FFT - (KBINS-1))  { float2 t = g_T2[M_FFT - i];  w = make_float2(t.x, -t.y); }
    g_kern[M_FFT + i] = w;
}

// --- small forward passes used only to build the chirp-kernel spectra ------
__global__ void __launch_bounds__(512) passA_small(const float2* __restrict__ in,
                                                   float2* __restrict__ out){
    __shared__ float2 sh[8 * SD];
    __shared__ float2 shW[512];
    __shared__ float2 shWN[512];
    int tid = threadIdx.x;
    size_t base = (size_t)blockIdx.y * M_FFT;
    int c0 = blockIdx.x * 8;
    shW[tid] = g_W512[tid]; shWN[tid] = g_WN[tid];
    const float2* gin = in + base;
    #pragma unroll
    for (int it = 0; it < 8; it++){
        int i = it*512 + tid;
        int r = i >> 3, cc = i & 7;
        sh[cc*SD + r] = gin[r*512 + c0 + cc];
    }
    __syncthreads();
    fft512_block<-1>(sh, shW, tid);
    float2* gout = out + base;
    #pragma unroll
    for (int it = 0; it < 8; it++){
        int i = it*512 + tid;
        int r = i >> 3, cc = i & 7;
        int t = r * (c0 + cc);
        float2 tw = cmul(shW[t >> 9], shWN[t & 511]);
        gout[r*512 + c0 + cc] = cmul(sh[cc*SD + r], tw);
    }
}

__global__ void __launch_bounds__(512) passB_small(float2* __restrict__ data){
    __shared__ float2 sh[8 * SD];
    __shared__ float2 shW[512];
    int tid = threadIdx.x;
    size_t base = (size_t)blockIdx.y * M_FFT + (size_t)blockIdx.x * 4096;
    shW[tid] = g_W512[tid];
    float2* g = data + base;
    #pragma unroll
    for (int it = 0; it < 8; it++){
        int i = it*512 + tid;
        sh[(i >> 9)*SD + (i & 511)] = g[i];
    }
    __syncthreads();
    fft512_block<-1>(sh, shW, tid);
    #pragma unroll
    for (int it = 0; it < 8; it++){
        int i = it*512 + tid;
        g[i] = sh[(i >> 9)*SD + (i & 511)];
    }
}

// ------------------- fused data-path kernels --------------------------------

// Forward passA with input chirp fused in the prologue (zero-pad beyond LEN).
// Prologue uses only global tables -> no shared race.
template<int LEN>
__global__ void __launch_bounds__(512) pA_fwd_input(float2* __restrict__ out,
                                                    const float* __restrict__ in){
    __shared__ float2 sh[8 * SD];
    __shared__ float2 shW[512];
    __shared__ float2 shWN[512];
    int tid = threadIdx.x;
    int p = blockIdx.y;
    int c0 = blockIdx.x * 8;
    shW[tid] = g_W512[tid]; shWN[tid] = g_WN[tid];
    const float* gin = in + (size_t)p * LEN;
    #pragma unroll
    for (int it = 0; it < 8; it++){
        int i = it*512 + tid;
        int r = i >> 3, cc = i & 7;
        int n = r*512 + c0 + cc;
        float2 v = make_float2(0.f, 0.f);
        if (n < LEN){
            float a = gin[n];
            float2 t = g_T1[n];
            v = make_float2(a * t.x, a * t.y);
        }
        sh[cc*SD + r] = v;
    }
    __syncthreads();
    fft512_block<-1>(sh, shW, tid);
    float2* gout = out + (size_t)p * M_FFT;
    #pragma unroll
    for (int it = 0; it < 8; it++){
        int i = it*512 + tid;
        int r = i >> 3, cc = i & 7;
        int t = r * (c0 + cc);
        float2 tw = cmul(shW[t >> 9], shWN[t & 511]);
        gout[r*512 + c0 + cc] = cmul(sh[cc*SD + r], tw);
    }
}

// passB_fwd * kspec * passB_inv fused (in place, block owns 8 rows).
__global__ void __launch_bounds__(512) fusedB_conv(float2* __restrict__ data,
                                                   const float2* __restrict__ kspec){
    __shared__ float2 sh[8 * SD];
    __shared__ float2 shW[512];
    int tid = threadIdx.x;
    size_t base = (size_t)blockIdx.y * M_FFT + (size_t)blockIdx.x * 4096;
    int lin0 = blockIdx.x * 4096;
    shW[tid] = g_W512[tid];
    float2* g = data + base;
    #pragma unroll
    for (int it = 0; it < 8; it++){
        int i = it*512 + tid;
        sh[(i >> 9)*SD + (i & 511)] = g[i];
    }
    __syncthreads();
    fft512_block<-1>(sh, shW, tid);
    #pragma unroll
    for (int it = 0; it < 8; it++){
        int i = it*512 + tid;
        int rr = i >> 9, c = i & 511;
        sh[rr*SD + c] = cmul(sh[rr*SD + c], kspec[lin0 + i]);
    }
    __syncthreads();
    fft512_block<+1>(sh, shW, tid);
    const float s = 1.0f / 512.0f;
    #pragma unroll
    for (int it = 0; it < 8; it++){
        int i = it*512 + tid;
        float2 v = sh[(i >> 9)*SD + (i & 511)];
        g[i] = make_float2(v.x * s, v.y * s);
    }
}

// Inverse-passA prologue: raw load -> sync -> in-place conj-twiddle -> sync.
// Each thread twiddles exactly the slots it loaded (no cross-thread sh hazard);
// the syncs order the shW/shWN table fill against the twiddle reads.
#define INV_PROLOGUE(GPTR)                                              \
    shW[tid] = g_W512[tid]; shWN[tid] = g_WN[tid];                      \
    _Pragma("unroll")                                                   \
    for (int it = 0; it < 8; it++){                                     \
        int i = it*512 + tid;                                           \
        int r = i >> 3, cc = i & 7;                                     \
        sh[cc*SD + r] = (GPTR)[r*512 + c0 + cc];                        \
    }                                                                   \
    __syncthreads();                                                    \
    _Pragma("unroll")                                                   \
    for (int it = 0; it < 8; it++){                                     \
        int i = it*512 + tid;                                           \
        int r = i >> 3, cc = i & 7;                                     \
        int t = r * (c0 + cc);                                          \
        float2 tw = cmul(shW[t >> 9], shWN[t & 511]);                   \
        tw.y = -tw.y;                                                   \
        sh[cc*SD + r] = cmul(sh[cc*SD + r], tw);                        \
    }                                                                   \
    __syncthreads();

// Inverse passA + H-spectrum extraction (writes only the KBINS slab).
__global__ void __launch_bounds__(512) pA_inv_H(const float2* __restrict__ in,
                                                float2* __restrict__ HS){
    __shared__ float2 sh[8 * SD];
    __shared__ float2 shW[512];
    __shared__ float2 shWN[512];
    int tid = threadIdx.x;
    int p = blockIdx.y;
    int c0 = blockIdx.x * 8;
    const float2* gin = in + (size_t)p * M_FFT;
    INV_PROLOGUE(gin)
    fft512_block<+1>(sh, shW, tid);
    const float s = 1.0f / 512.0f;
    #pragma unroll
    for (int it = 0; it < 8; it++){
        int i = it*512 + tid;
        int r = i >> 3, cc = i & 7;
        int k = r*512 + c0 + cc;
        if (k < KBINS){
            float2 v = sh[cc*SD + r];
            v.x *= s; v.y *= s;
            HS[(size_t)p * KBINS + k] = cmul(g_T1[k], v);
        }
    }
}

// CZT-X inverse passA + (Y = X*H, chirps, DC/Nyquist fix) + CZT-3 forward passA.
__global__ void __launch_bounds__(512) fused_inv_d_fwd(float2* __restrict__ data,
                                                       const float2* __restrict__ HS){
    __shared__ float2 sh[8 * SD];
    __shared__ float2 shW[512];
    __shared__ float2 shWN[512];
    int tid = threadIdx.x;
    int p = blockIdx.y;
    int c0 = blockIdx.x * 8;
    float2* g = data + (size_t)p * M_FFT;
    INV_PROLOGUE(g)
    fft512_block<+1>(sh, shW, tid);
    const float s = 1.0f / 512.0f;
    #pragma unroll
    for (int it = 0; it < 8; it++){
        int i = it*512 + tid;
        int r = i >> 3, cc = i & 7;
        int k = r*512 + c0 + cc;
        float2 d = make_float2(0.f, 0.f);
        if (k < KBINS){
            float2 a = sh[cc*SD + r];
            a.x *= s; a.y *= s;
            float2 X = cmul(g_T1[k], a);
            float2 Y = cmul(X, HS[(size_t)p * KBINS + k]);
            if (k == 0 || k == KBINS - 1) Y = make_float2(0.5f * Y.x, 0.f);
            d = cmul(Y, g_T2[k]);
        }
        sh[cc*SD + r] = d;   // own slot, no cross-thread hazard
    }
    __syncthreads();
    fft512_block<-1>(sh, shW, tid);
    #pragma unroll
    for (int it = 0; it < 8; it++){
        int i = it*512 + tid;
        int r = i >> 3, cc = i & 7;
        int t = r * (c0 + cc);
        float2 tw = cmul(shW[t >> 9], shWN[t & 511]);
        g[r*512 + c0 + cc] = cmul(sh[cc*SD + r], tw);
    }
}

// Inverse passA + final real output (writes only the LX real samples).
__global__ void __launch_bounds__(512) pA_inv_out(const float2* __restrict__ in,
                                                  float* __restrict__ out){
    __shared__ float2 sh[8 * SD];
    __shared__ float2 shW[512];
    __shared__ float2 shWN[512];
    int tid = threadIdx.x;
    int p = blockIdx.y;
    int c0 = blockIdx.x * 8;
    const float2* gin = in + (size_t)p * M_FFT;
    INV_PROLOGUE(gin)
    fft512_block<+1>(sh, shW, tid);
    const float sc = (2.0f / (float)N2C) * (1.0f / 512.0f);
    #pragma unroll
    for (int it = 0; it < 8; it++){
        int i = it*512 + tid;
        int r = i >> 3, cc = i & 7;
        int n = r*512 + c0 + cc;
        if (n < LX){
            float2 v = sh[cc*SD + r];
            float2 T = g_T2[n];
            out[(size_t)p * LX + n] = sc * (T.x * v.x - T.y * v.y);
        }
    }
}

// ------------------------- launch -------------------------------------------
extern "C" void kernel_launch(void* const* d_in, const int* in_sizes, int n_in,
                              void* d_out, int out_size){
    (void)in_sizes; (void)n_in; (void)out_size;
    const float* x = (const float*)d_in[0];
    const float* h = (const float*)d_in[1];
    float* out = (float*)d_out;

    float2 *bufA, *hs, *kern, *kspec;
    cudaGetSymbolAddress((void**)&bufA, g_bufA);
    cudaGetSymbolAddress((void**)&hs,   g_HS);
    cudaGetSymbolAddress((void**)&kern, g_kern);
    cudaGetSymbolAddress((void**)&kspec,g_kspec);

    const dim3 fgrid(64, NPAIR);
    const dim3 kgrid(64, 2);

    // 0. tables + chirp kernels + their spectra
    init_tables<<<512, 256>>>();
    build_kern<<<M_FFT / 256, 256>>>();
    passA_small<<<kgrid, 512>>>(kern, kspec);
    passB_small<<<kgrid, 512>>>(kspec);

    // 1. H path: CZT of h on the N1 grid -> g_HS
    pA_fwd_input<LH><<<fgrid, 512>>>(bufA, h);
    fusedB_conv<<<fgrid, 512>>>(bufA, kspec);            // * B1
    pA_inv_H<<<fgrid, 512>>>(bufA, hs);

    // 2. X path forward CZT
    pA_fwd_input<LX><<<fgrid, 512>>>(bufA, x);
    fusedB_conv<<<fgrid, 512>>>(bufA, kspec);            // * B1

    // 3. inverse passA -> Y=X*H pointwise -> forward passA of synthesis CZT
    fused_inv_d_fwd<<<fgrid, 512>>>(bufA, hs);
    fusedB_conv<<<fgrid, 512>>>(bufA, kspec + M_FFT);    // * B2

    // 4. inverse passA + final real output
    pA_inv_out<<<fgrid, 512>>>(bufA, out);
}

// round 4
// speedup vs baseline: 2.0083x; 1.6316x over previous
#include <cuda_runtime.h>
#include <math.h>

// ---------------------------------------------------------------------------
// Causal FFT convolution matching:
//   X = rfft(x, n=163839); H = rfft(h, n=163839); Y = X*H
//   y = irfft(Y)   (default n = 163838 <-- mismatched grids), out = y[:131072]
// Bluestein CZTs on a 2^18 four-step FFT (512x512), fused pipeline.
// R4: XOR-swizzled shared layout (kills 4..16-way bank conflicts),
//     computed twiddles (sincospif + power chains, no shared tables),
//     float4 global I/O in the row-FFT kernels.
// ---------------------------------------------------------------------------

#define M_FFT  262144
#define NPAIR  128
#define LX     131072
#define LH     32768
#define KBINS  81920
#define N1C    163839
#define N2C    163838
#define SD     516

__device__ __align__(16) float2 g_bufA[(size_t)NPAIR * M_FFT];   // 268 MB
__device__ __align__(16) float2 g_HS [(size_t)NPAIR * KBINS];    // 84 MB
__device__ __align__(16) float2 g_T1 [LX];
__device__ __align__(16) float2 g_T2 [LX];
__device__ __align__(16) float2 g_kern [2 * M_FFT];
__device__ __align__(16) float2 g_kspec[2 * M_FFT];

__device__ __forceinline__ int SWZ(int m){ return m ^ ((m >> 4) & 15); }

// ------------------------- complex helpers ---------------------------------
__device__ __forceinline__ float2 cadd(float2 a, float2 b){ return make_float2(a.x+b.x, a.y+b.y); }
__device__ __forceinline__ float2 csub(float2 a, float2 b){ return make_float2(a.x-b.x, a.y-b.y); }
__device__ __forceinline__ float2 cmul(float2 a, float2 b){
    return make_float2(a.x*b.x - a.y*b.y, a.x*b.y + a.y*b.x);
}
template<int SIGN> __device__ __forceinline__ float2 mul_i(float2 a){
    return (SIGN < 0) ? make_float2(a.y, -a.x) : make_float2(-a.y, a.x);
}

template<int SIGN>
__device__ __forceinline__ void fft4(float2 &x0, float2 &x1, float2 &x2, float2 &x3){
    float2 t0 = cadd(x0, x2), t1 = csub(x0, x2);
    float2 t2 = cadd(x1, x3), t3 = csub(x1, x3);
    float2 t3r = mul_i<SIGN>(t3);
    x0 = cadd(t0, t2);
    x2 = csub(t0, t2);
    x1 = cadd(t1, t3r);
    x3 = csub(t1, t3r);
}

template<int SIGN>
__device__ __forceinline__ void fft8(float2 u[8]){
    float2 e0=u[0], e1=u[2], e2=u[4], e3=u[6];
    float2 o0=u[1], o1=u[3], o2=u[5], o3=u[7];
    fft4<SIGN>(e0,e1,e2,e3);
    fft4<SIGN>(o0,o1,o2,o3);
    const float s2 = 0.70710678118654752440f;
    float2 w1 = make_float2( s2, SIGN * s2);
    float2 w3 = make_float2(-s2, SIGN * s2);
    o1 = cmul(o1, w1);
    o2 = mul_i<SIGN>(o2);
    o3 = cmul(o3, w3);
    u[0]=cadd(e0,o0); u[4]=csub(e0,o0);
    u[1]=cadd(e1,o1); u[5]=csub(e1,o1);
    u[2]=cadd(e2,o2); u[6]=csub(e2,o2);
    u[3]=cadd(e3,o3); u[7]=csub(e3,o3);
}

// Natural-order in/out FFT-512 on SWZ-swizzled shared rows.
// 8 FFTs per 512-thread block. Caller syncs after filling shared.
template<int SIGN>
__device__ void fft512_block(float2* s, int tid){
    int f = tid >> 6;
    int l = tid & 63;
    float2* sp = s + f * SD;
    float2 u[8];

    { // stage 0: digit-reversed gather, radix-8
        #pragma unroll
        for (int q = 0; q < 8; q++){
            int src = q*64 + (l & 7)*8 + (l >> 3);
            u[q] = sp[SWZ(src)];
        }
        fft8<SIGN>(u);
        __syncthreads();
        #pragma unroll
        for (int r = 0; r < 8; r++) sp[SWZ(l*8 + r)] = u[r];
    }
    __syncthreads();

    { // stage 1 (m=64): twiddle w^q, w = exp(SIGN*i*pi*j/32)
        int gg = l >> 3, j = l & 7;
        int base = gg*64 + j;
        #pragma unroll
        for (int q = 0; q < 8; q++) u[q] = sp[SWZ(base + q*8)];
        float sn, cs; sincospif((float)j * (1.0f/32.0f), &sn, &cs);
        float2 w1 = make_float2(cs, SIGN * sn), w = w1;
        #pragma unroll
        for (int q = 1; q < 8; q++){ u[q] = cmul(u[q], w); w = cmul(w, w1); }
        fft8<SIGN>(u);
        #pragma unroll
        for (int r = 0; r < 8; r++) sp[SWZ(base + r*8)] = u[r];
    }
    __syncthreads();

    { // stage 2 (m=512): twiddle w^q, w = exp(SIGN*i*pi*j/256)
        int j = l;
        #pragma unroll
        for (int q = 0; q < 8; q++) u[q] = sp[SWZ(j + q*64)];
        float sn, cs; sincospif((float)j * (1.0f/256.0f), &sn, &cs);
        float2 w1 = make_float2(cs, SIGN * sn), w = w1;
        #pragma unroll
        for (int q = 1; q < 8; q++){ u[q] = cmul(u[q], w); w = cmul(w, w1); }
        fft8<SIGN>(u);
        #pragma unroll
        for (int r = 0; r < 8; r++) sp[SWZ(j + r*64)] = u[r];
    }
    __syncthreads();
}

// ------------------------- table / kernel construction ---------------------
__global__ void init_tables(){
    int i = blockIdx.x * blockDim.x + threadIdx.x;
    if (i < LX){
        unsigned long long ii = (unsigned long long)i * (unsigned long long)i;
        double s, c;
        double a1 = (double)(ii % (2ULL * N1C)) / (double)N1C;
        sincospi(a1, &s, &c);
        g_T1[i] = make_float2((float)c, (float)(-s));
        double a2 = (double)(ii % (2ULL * N2C)) / (double)N2C;
        sincospi(a2, &s, &c);
        g_T2[i] = make_float2((float)c, (float)s);
    }
}

__global__ void build_kern(){
    int i = blockIdx.x * blockDim.x + threadIdx.x;
    if (i >= M_FFT) return;
    float2 v = make_float2(0.f, 0.f);
    if (i <= KBINS - 1)               { float2 t = g_T1[i];          v = make_float2(t.x, -t.y); }
    else if (i >= M_FFT - (LX - 1))   { float2 t = g_T1[M_FFT - i];  v = make_float2(t.x, -t.y); }
    g_kern[i] = v;
    float2 w = make_float2(0.f, 0.f);
    if (i <= LX - 1)                  { float2 t = g_T2[i];          w = make_float2(t.x, -t.y); }
    else if (i >= M_FFT - (KBINS-1))  { float2 t = g_T2[M_FFT - i];  w = make_float2(t.x, -t.y); }
    g_kern[M_FFT + i] = w;
}

// Four-step twiddle helpers: per-thread incremental recurrence.
// tw(it) = exp(sign * 2*pi*i * (it*64+rt)*c / 2^18); step = exp(sign*i*pi*c/2048)
__device__ __forceinline__ void fourstep_init(int rt, int c, float sgn,
                                              float2 &tw, float2 &ws){
    float sa, ca, sb, cb;
    sincospif((float)(rt * c) * (1.0f/131072.0f), &sa, &ca);
    sincospif((float)c * (1.0f/2048.0f), &sb, &cb);
    tw = make_float2(ca, sgn * sa);
    ws = make_float2(cb, sgn * sb);
}

// --- small passes for the chirp-kernel spectra (batch 2) --------------------
__global__ void __launch_bounds__(512) passA_small(const float2* __restrict__ in,
                                                   float2* __restrict__ out){
    __shared__ float2 sh[8 * SD];
    int tid = threadIdx.x;
    size_t base = (size_t)blockIdx.y * M_FFT;
    int c0 = blockIdx.x * 8;
    int cc = tid & 7, rt = tid >> 3, c = c0 + cc;
    const float2* gin = in + base;
    #pragma unroll
    for (int it = 0; it < 8; it++){
        int r = it*64 + rt;
        sh[cc*SD + SWZ(r)] = gin[r*512 + c];
    }
    __syncthreads();
    fft512_block<-1>(sh, tid);
    float2 tw, ws; fourstep_init(rt, c, -1.f, tw, ws);
    float2* gout = out + base;
    #pragma unroll
    for (int it = 0; it < 8; it++){
        int r = it*64 + rt;
        gout[r*512 + c] = cmul(sh[cc*SD + SWZ(r)], tw);
        tw = cmul(tw, ws);
    }
}

__global__ void __launch_bounds__(512) passB_small(float2* __restrict__ data){
    __shared__ float2 sh[8 * SD];
    int tid = threadIdx.x;
    size_t base = (size_t)blockIdx.y * M_FFT + (size_t)blockIdx.x * 4096;
    float2* g = data + base;
    #pragma unroll
    for (int it = 0; it < 8; it++){
        sh[it*SD + SWZ(tid)] = g[it*512 + tid];
    }
    __syncthreads();
    fft512_block<-1>(sh, tid);
    #pragma unroll
    for (int it = 0; it < 8; it++){
        g[it*512 + tid] = sh[it*SD + SWZ(tid)];
    }
}

// ------------------- fused data-path kernels --------------------------------

// Forward passA with input chirp fused in the prologue (zero-pad beyond LEN).
template<int LEN>
__global__ void __launch_bounds__(512) pA_fwd_input(float2* __restrict__ out,
                                                    const float* __restrict__ in){
    __shared__ float2 sh[8 * SD];
    int tid = threadIdx.x;
    int p = blockIdx.y;
    int c0 = blockIdx.x * 8;
    int cc = tid & 7, rt = tid >> 3, c = c0 + cc;
    const float* gin = in + (size_t)p * LEN;
    #pragma unroll
    for (int it = 0; it < 8; it++){
        int r = it*64 + rt;
        int n = r*512 + c;
        float2 v = make_float2(0.f, 0.f);
        if (n < LEN){
            float a = gin[n];
            float2 t = g_T1[n];
            v = make_float2(a * t.x, a * t.y);
        }
        sh[cc*SD + SWZ(r)] = v;
    }
    __syncthreads();
    fft512_block<-1>(sh, tid);
    float2 tw, ws; fourstep_init(rt, c, -1.f, tw, ws);
    float2* gout = out + (size_t)p * M_FFT;
    #pragma unroll
    for (int it = 0; it < 8; it++){
        int r = it*64 + rt;
        gout[r*512 + c] = cmul(sh[cc*SD + SWZ(r)], tw);
        tw = cmul(tw, ws);
    }
}

// passB_fwd * kspec * passB_inv fused (in place, block owns 8 rows). float4 I/O.
__global__ void __launch_bounds__(512) fusedB_conv(float2* __restrict__ data,
                                                   const float2* __restrict__ kspec){
    __shared__ float2 sh[8 * SD];
    int tid = threadIdx.x;
    size_t base = (size_t)blockIdx.y * M_FFT + (size_t)blockIdx.x * 4096;
    int lin0 = blockIdx.x * 4096;
    float2* g = data + base;
    const float4* g4 = (const float4*)g;
    float4* g4w = (float4*)g;
    const float4* k4 = (const float4*)(kspec + lin0);

    #pragma unroll
    for (int it = 0; it < 4; it++){
        int idx = it*512 + tid;
        float4 v = g4[idx];
        int e = (idx*2) & 511;
        int row = idx >> 8;
        float2* rp = sh + row*SD;
        rp[SWZ(e)]     = make_float2(v.x, v.y);
        rp[SWZ(e + 1)] = make_float2(v.z, v.w);
    }
    __syncthreads();
    fft512_block<-1>(sh, tid);
    #pragma unroll
    for (int it = 0; it < 4; it++){
        int idx = it*512 + tid;
        float4 kv = k4[idx];
        int e = (idx*2) & 511;
        int row = idx >> 8;
        float2* rp = sh + row*SD;
        rp[SWZ(e)]     = cmul(rp[SWZ(e)],     make_float2(kv.x, kv.y));
        rp[SWZ(e + 1)] = cmul(rp[SWZ(e + 1)], make_float2(kv.z, kv.w));
    }
    __syncthreads();
    fft512_block<+1>(sh, tid);
    const float s = 1.0f / 512.0f;
    #pragma unroll
    for (int it = 0; it < 4; it++){
        int idx = it*512 + tid;
        int e = (idx*2) & 511;
        int row = idx >> 8;
        float2* rp = sh + row*SD;
        float2 a = rp[SWZ(e)];
        float2 b = rp[SWZ(e + 1)];
        g4w[idx] = make_float4(a.x*s, a.y*s, b.x*s, b.y*s);
    }
}

// Inverse passA + H-spectrum extraction (writes only the KBINS slab).
__global__ void __launch_bounds__(512) pA_inv_H(const float2* __restrict__ in,
                                                float2* __restrict__ HS){
    __shared__ float2 sh[8 * SD];
    int tid = threadIdx.x;
    int p = blockIdx.y;
    int c0 = blockIdx.x * 8;
    int cc = tid & 7, rt = tid >> 3, c = c0 + cc;
    const float2* gin = in + (size_t)p * M_FFT;
    {
        float2 tw, ws; fourstep_init(rt, c, +1.f, tw, ws);
        #pragma unroll
        for (int it = 0; it < 8; it++){
            int r = it*64 + rt;
            sh[cc*SD + SWZ(r)] = cmul(gin[r*512 + c], tw);
            tw = cmul(tw, ws);
        }
    }
    __syncthreads();
    fft512_block<+1>(sh, tid);
    const float s = 1.0f / 512.0f;
    #pragma unroll
    for (int it = 0; it < 8; it++){
        int r = it*64 + rt;
        int k = r*512 + c;
        if (k < KBINS){
            float2 v = sh[cc*SD + SWZ(r)];
            v.x *= s; v.y *= s;
            HS[(size_t)p * KBINS + k] = cmul(g_T1[k], v);
        }
    }
}

// CZT-X inverse passA + (Y = X*H, chirps, DC/Nyquist fix) + CZT-3 forward passA.
__global__ void __launch_bounds__(512) fused_inv_d_fwd(float2* __restrict__ data,
                                                       const float2* __restrict__ HS){
    __shared__ float2 sh[8 * SD];
    int tid = threadIdx.x;
    int p = blockIdx.y;
    int c0 = blockIdx.x * 8;
    int cc = tid & 7, rt = tid >> 3, c = c0 + cc;
    float2* g = data + (size_t)p * M_FFT;
    {
        float2 tw, ws; fourstep_init(rt, c, +1.f, tw, ws);
        #pragma unroll
        for (int it = 0; it < 8; it++){
            int r = it*64 + rt;
            sh[cc*SD + SWZ(r)] = cmul(g[r*512 + c], tw);
            tw = cmul(tw, ws);
        }
    }
    __syncthreads();
    fft512_block<+1>(sh, tid);
    const float s = 1.0f / 512.0f;
    #pragma unroll
    for (int it = 0; it < 8; it++){
        int r = it*64 + rt;
        int k = r*512 + c;
        float2 d = make_float2(0.f, 0.f);
        if (k < KBINS){
            float2 a = sh[cc*SD + SWZ(r)];
            a.x *= s; a.y *= s;
            float2 X = cmul(g_T1[k], a);
            float2 Y = cmul(X, HS[(size_t)p * KBINS + k]);
            if (k == 0 || k == KBINS - 1) Y = make_float2(0.5f * Y.x, 0.f);
            d = cmul(Y, g_T2[k]);
        }
        sh[cc*SD + SWZ(r)] = d;   // own slot
    }
    __syncthreads();
    fft512_block<-1>(sh, tid);
    float2 tw, ws; fourstep_init(rt, c, -1.f, tw, ws);
    #pragma unroll
    for (int it = 0; it < 8; it++){
        int r = it*64 + rt;
        g[r*512 + c] = cmul(sh[cc*SD + SWZ(r)], tw);
        tw = cmul(tw, ws);
    }
}

// Inverse passA + final real output (writes only the LX real samples).
__global__ void __launch_bounds__(512) pA_inv_out(const float2* __restrict__ in,
                                                  float* __restrict__ out){
    __shared__ float2 sh[8 * SD];
    int tid = threadIdx.x;
    int p = blockIdx.y;
    int c0 = blockIdx.x * 8;
    int cc = tid & 7, rt = tid >> 3, c = c0 + cc;
    const float2* gin = in + (size_t)p * M_FFT;
    {
        float2 tw, ws; fourstep_init(rt, c, +1.f, tw, ws);
        #pragma unroll
        for (int it = 0; it < 8; it++){
            int r = it*64 + rt;
            sh[cc*SD + SWZ(r)] = cmul(gin[r*512 + c], tw);
            tw = cmul(tw, ws);
        }
    }
    __syncthreads();
    fft512_block<+1>(sh, tid);
    const float sc = (2.0f / (float)N2C) * (1.0f / 512.0f);
    #pragma unroll
    for (int it = 0; it < 8; it++){
        int r = it*64 + rt;
        int n = r*512 + c;
        if (n < LX){
            float2 v = sh[cc*SD + SWZ(r)];
            float2 T = g_T2[n];
            out[(size_t)p * LX + n] = sc * (T.x * v.x - T.y * v.y);
        }
    }
}

// ------------------------- launch -------------------------------------------
extern "C" void kernel_launch(void* const* d_in, const int* in_sizes, int n_in,
                              void* d_out, int out_size){
    (void)in_sizes; (void)n_in; (void)out_size;
    const float* x = (const float*)d_in[0];
    const float* h = (const float*)d_in[1];
    float* out = (float*)d_out;

    float2 *bufA, *hs, *kern, *kspec;
    cudaGetSymbolAddress((void**)&bufA, g_bufA);
    cudaGetSymbolAddress((void**)&hs,   g_HS);
    cudaGetSymbolAddress((void**)&kern, g_kern);
    cudaGetSymbolAddress((void**)&kspec,g_kspec);

    const dim3 fgrid(64, NPAIR);
    const dim3 kgrid(64, 2);

    // 0. tables + chirp kernels + their spectra
    init_tables<<<512, 256>>>();
    build_kern<<<M_FFT / 256, 256>>>();
    passA_small<<<kgrid, 512>>>(kern, kspec);
    passB_small<<<kgrid, 512>>>(kspec);

    // 1. H path: CZT of h on the N1 grid -> g_HS
    pA_fwd_input<LH><<<fgrid, 512>>>(bufA, h);
    fusedB_conv<<<fgrid, 512>>>(bufA, kspec);            // * B1
    pA_inv_H<<<fgrid, 512>>>(bufA, hs);

    // 2. X path forward CZT
    pA_fwd_input<LX><<<fgrid, 512>>>(bufA, x);
    fusedB_conv<<<fgrid, 512>>>(bufA, kspec);            // * B1

    // 3. inverse passA -> Y=X*H pointwise -> forward passA of synthesis CZT
    fused_inv_d_fwd<<<fgrid, 512>>>(bufA, hs);
    fusedB_conv<<<fgrid, 512>>>(bufA, kspec + M_FFT);    // * B2

    // 4. inverse passA + final real output
    pA_inv_out<<<fgrid, 512>>>(bufA, out);
}

// round 5
// speedup vs baseline: 2.0710x; 1.0312x over previous
#include <cuda_runtime.h>
#include <math.h>

// ---------------------------------------------------------------------------
// Causal FFT convolution matching:
//   X = rfft(x, n=163839); H = rfft(h, n=163839); Y = X*H
//   y = irfft(Y)   (default n = 163838 <-- mismatched grids), out = y[:131072]
// Bluestein CZTs on a 2^18 four-step FFT (512x512), fused pipeline.
// R5: hoisted stage twiddles (sincospif once per kernel, not per FFT call),
//     register-resident stage-2 output + in-register kspec multiply in the
//     row-FFT convolution kernel (-25% shared traffic there).
// ---------------------------------------------------------------------------

#define M_FFT  262144
#define NPAIR  128
#define LX     131072
#define LH     32768
#define KBINS  81920
#define N1C    163839
#define N2C    163838
#define SD     516

__device__ __align__(16) float2 g_bufA[(size_t)NPAIR * M_FFT];   // 268 MB
__device__ __align__(16) float2 g_HS [(size_t)NPAIR * KBINS];    // 84 MB
__device__ __align__(16) float2 g_T1 [LX];
__device__ __align__(16) float2 g_T2 [LX];
__device__ __align__(16) float2 g_kern [2 * M_FFT];
__device__ __align__(16) float2 g_kspec[2 * M_FFT];

__device__ __forceinline__ int SWZ(int m){ return m ^ ((m >> 4) & 15); }

// ------------------------- complex helpers ---------------------------------
__device__ __forceinline__ float2 cadd(float2 a, float2 b){ return make_float2(a.x+b.x, a.y+b.y); }
__device__ __forceinline__ float2 csub(float2 a, float2 b){ return make_float2(a.x-b.x, a.y-b.y); }
__device__ __forceinline__ float2 cconj(float2 a){ return make_float2(a.x, -a.y); }
__device__ __forceinline__ float2 cmul(float2 a, float2 b){
    return make_float2(a.x*b.x - a.y*b.y, a.x*b.y + a.y*b.x);
}
template<int SIGN> __device__ __forceinline__ float2 mul_i(float2 a){
    return (SIGN < 0) ? make_float2(a.y, -a.x) : make_float2(-a.y, a.x);
}

template<int SIGN>
__device__ __forceinline__ void fft4(float2 &x0, float2 &x1, float2 &x2, float2 &x3){
    float2 t0 = cadd(x0, x2), t1 = csub(x0, x2);
    float2 t2 = cadd(x1, x3), t3 = csub(x1, x3);
    float2 t3r = mul_i<SIGN>(t3);
    x0 = cadd(t0, t2);
    x2 = csub(t0, t2);
    x1 = cadd(t1, t3r);
    x3 = csub(t1, t3r);
}

template<int SIGN>
__device__ __forceinline__ void fft8(float2 u[8]){
    float2 e0=u[0], e1=u[2], e2=u[4], e3=u[6];
    float2 o0=u[1], o1=u[3], o2=u[5], o3=u[7];
    fft4<SIGN>(e0,e1,e2,e3);
    fft4<SIGN>(o0,o1,o2,o3);
    const float s2 = 0.70710678118654752440f;
    float2 w1 = make_float2( s2, SIGN * s2);
    float2 w3 = make_float2(-s2, SIGN * s2);
    o1 = cmul(o1, w1);
    o2 = mul_i<SIGN>(o2);
    o3 = cmul(o3, w3);
    u[0]=cadd(e0,o0); u[4]=csub(e0,o0);
    u[1]=cadd(e1,o1); u[5]=csub(e1,o1);
    u[2]=cadd(e2,o2); u[6]=csub(e2,o2);
    u[3]=cadd(e3,o3); u[7]=csub(e3,o3);
}

// Hoisted per-thread stage twiddles (forward sign; conjugated for inverse).
// stage1: exp(-i*pi*(tid&7)/32), stage2: exp(-i*pi*(tid&63)/256).
__device__ __forceinline__ void stage_twiddles(int tid, float2 &w1s1, float2 &w1s2){
    float sn, cs;
    sincospif((float)(tid & 7) * (1.0f/32.0f), &sn, &cs);
    w1s1 = make_float2(cs, -sn);
    sincospif((float)(tid & 63) * (1.0f/256.0f), &sn, &cs);
    w1s2 = make_float2(cs, -sn);
}

// Stages 0+1 of the 512-pt FFT (shared in, shared out). Internal syncs.
template<int SIGN>
__device__ __forceinline__ void fft512_s01(float2* sp, int l, float2 w1f_s1){
    float2 u[8];
    { // stage 0: digit-reversed gather, radix-8
        #pragma unroll
        for (int q = 0; q < 8; q++){
            int src = q*64 + (l & 7)*8 + (l >> 3);
            u[q] = sp[SWZ(src)];
        }
        fft8<SIGN>(u);
        __syncthreads();
        #pragma unroll
        for (int r = 0; r < 8; r++) sp[SWZ(l*8 + r)] = u[r];
    }
    __syncthreads();
    { // stage 1 (m=64)
        int gg = l >> 3, j = l & 7;
        int base = gg*64 + j;
        #pragma unroll
        for (int q = 0; q < 8; q++) u[q] = sp[SWZ(base + q*8)];
        float2 w1 = (SIGN < 0) ? w1f_s1 : cconj(w1f_s1);
        float2 w = w1;
        #pragma unroll
        for (int q = 1; q < 8; q++){ u[q] = cmul(u[q], w); w = cmul(w, w1); }
        fft8<SIGN>(u);
        #pragma unroll
        for (int r = 0; r < 8; r++) sp[SWZ(base + r*8)] = u[r];
    }
    __syncthreads();
}

// Full FFT-512, shared in / shared out (for passA-type kernels).
template<int SIGN>
__device__ void fft512_block(float2* s, int tid, float2 w1f_s1, float2 w1f_s2){
    int f = tid >> 6, l = tid & 63;
    float2* sp = s + f * SD;
    fft512_s01<SIGN>(sp, l, w1f_s1);
    float2 u[8];
    { // stage 2 (m=512)
        int j = l;
        #pragma unroll
        for (int q = 0; q < 8; q++) u[q] = sp[SWZ(j + q*64)];
        float2 w1 = (SIGN < 0) ? w1f_s2 : cconj(w1f_s2);
        float2 w = w1;
        #pragma unroll
        for (int q = 1; q < 8; q++){ u[q] = cmul(u[q], w); w = cmul(w, w1); }
        fft8<SIGN>(u);
        #pragma unroll
        for (int r = 0; r < 8; r++) sp[SWZ(j + r*64)] = u[r];
    }
    __syncthreads();
}

// Full FFT-512, shared in / REGISTER out. u[r] = spectrum element (l + 64r)
// of sub-FFT f. No trailing write or sync: caller must __syncthreads()
// before reusing the shared tile.
template<int SIGN>
__device__ void fft512_reg(float2* s, int tid, float2 w1f_s1, float2 w1f_s2,
                           float2 u[8]){
    int f = tid >> 6, l = tid & 63;
    float2* sp = s + f * SD;
    fft512_s01<SIGN>(sp, l, w1f_s1);
    int j = l;
    #pragma unroll
    for (int q = 0; q < 8; q++) u[q] = sp[SWZ(j + q*64)];
    float2 w1 = (SIGN < 0) ? w1f_s2 : cconj(w1f_s2);
    float2 w = w1;
    #pragma unroll
    for (int q = 1; q < 8; q++){ u[q] = cmul(u[q], w); w = cmul(w, w1); }
    fft8<SIGN>(u);
}

// ------------------------- table / kernel construction ---------------------
__global__ void init_tables(){
    int i = blockIdx.x * blockDim.x + threadIdx.x;
    if (i < LX){
        unsigned long long ii = (unsigned long long)i * (unsigned long long)i;
        double s, c;
        double a1 = (double)(ii % (2ULL * N1C)) / (double)N1C;
        sincospi(a1, &s, &c);
        g_T1[i] = make_float2((float)c, (float)(-s));
        double a2 = (double)(ii % (2ULL * N2C)) / (double)N2C;
        sincospi(a2, &s, &c);
        g_T2[i] = make_float2((float)c, (float)s);
    }
}

__global__ void build_kern(){
    int i = blockIdx.x * blockDim.x + threadIdx.x;
    if (i >= M_FFT) return;
    float2 v = make_float2(0.f, 0.f);
    if (i <= KBINS - 1)               { float2 t = g_T1[i];          v = make_float2(t.x, -t.y); }
    else if (i >= M_FFT - (LX - 1))   { float2 t = g_T1[M_FFT - i];  v = make_float2(t.x, -t.y); }
    g_kern[i] = v;
    float2 w = make_float2(0.f, 0.f);
    if (i <= LX - 1)                  { float2 t = g_T2[i];          w = make_float2(t.x, -t.y); }
    else if (i >= M_FFT - (KBINS-1))  { float2 t = g_T2[M_FFT - i];  w = make_float2(t.x, -t.y); }
    g_kern[M_FFT + i] = w;
}

// Four-step twiddle recurrence init.
// tw = exp(sgn*2pi*i * r0*c / 2^18); step = exp(sgn*2pi*i * 64*c / 2^18)
__device__ __forceinline__ void fourstep_init(int r0, int c, float sgn,
                                              float2 &tw, float2 &ws){
    float sa, ca, sb, cb;
    sincospif((float)(r0 * c) * (1.0f/131072.0f), &sa, &ca);
    sincospif((float)c * (1.0f/2048.0f), &sb, &cb);
    tw = make_float2(ca, sgn * sa);
    ws = make_float2(cb, sgn * sb);
}

// --- small passes for the chirp-kernel spectra (batch 2) --------------------
__global__ void __launch_bounds__(512) passA_small(const float2* __restrict__ in,
                                                   float2* __restrict__ out){
    __shared__ float2 sh[8 * SD];
    int tid = threadIdx.x;
    float2 w1s1, w1s2; stage_twiddles(tid, w1s1, w1s2);
    size_t base = (size_t)blockIdx.y * M_FFT;
    int c0 = blockIdx.x * 8;
    int cc = tid & 7, rt = tid >> 3, c = c0 + cc;
    const float2* gin = in + base;
    #pragma unroll
    for (int it = 0; it < 8; it++){
        int r = it*64 + rt;
        sh[cc*SD + SWZ(r)] = gin[r*512 + c];
    }
    __syncthreads();
    fft512_block<-1>(sh, tid, w1s1, w1s2);
    float2 tw, ws; fourstep_init(rt, c, -1.f, tw, ws);
    float2* gout = out + base;
    #pragma unroll
    for (int it = 0; it < 8; it++){
        int r = it*64 + rt;
        gout[r*512 + c] = cmul(sh[cc*SD + SWZ(r)], tw);
        tw = cmul(tw, ws);
    }
}

__global__ void __launch_bounds__(512) passB_small(float2* __restrict__ data){
    __shared__ float2 sh[8 * SD];
    int tid = threadIdx.x;
    float2 w1s1, w1s2; stage_twiddles(tid, w1s1, w1s2);
    size_t base = (size_t)blockIdx.y * M_FFT + (size_t)blockIdx.x * 4096;
    float2* g = data + base;
    #pragma unroll
    for (int it = 0; it < 8; it++){
        sh[it*SD + SWZ(tid)] = g[it*512 + tid];
    }
    __syncthreads();
    fft512_block<-1>(sh, tid, w1s1, w1s2);
    #pragma unroll
    for (int it = 0; it < 8; it++){
        g[it*512 + tid] = sh[it*SD + SWZ(tid)];
    }
}

// ------------------- fused data-path kernels --------------------------------

// Forward passA with input chirp fused in the prologue (zero-pad beyond LEN).
template<int LEN>
__global__ void __launch_bounds__(512) pA_fwd_input(float2* __restrict__ out,
                                                    const float* __restrict__ in){
    __shared__ float2 sh[8 * SD];
    int tid = threadIdx.x;
    float2 w1s1, w1s2; stage_twiddles(tid, w1s1, w1s2);
    int p = blockIdx.y;
    int c0 = blockIdx.x * 8;
    int cc = tid & 7, rt = tid >> 3, c = c0 + cc;
    const float* gin = in + (size_t)p * LEN;
    #pragma unroll
    for (int it = 0; it < 8; it++){
        int r = it*64 + rt;
        int n = r*512 + c;
        float2 v = make_float2(0.f, 0.f);
        if (n < LEN){
            float a = gin[n];
            float2 t = g_T1[n];
            v = make_float2(a * t.x, a * t.y);
        }
        sh[cc*SD + SWZ(r)] = v;
    }
    __syncthreads();
    fft512_block<-1>(sh, tid, w1s1, w1s2);
    float2 tw, ws; fourstep_init(rt, c, -1.f, tw, ws);
    float2* gout = out + (size_t)p * M_FFT;
    #pragma unroll
    for (int it = 0; it < 8; it++){
        int r = it*64 + rt;
        gout[r*512 + c] = cmul(sh[cc*SD + SWZ(r)], tw);
        tw = cmul(tw, ws);
    }
}

// passB_fwd * kspec * passB_inv fused in place; float4 input staging,
// register-resident stage-2 output + in-register spectral multiply.
__global__ void __launch_bounds__(512) fusedB_conv(float2* __restrict__ data,
                                                   const float2* __restrict__ kspec){
    __shared__ float2 sh[8 * SD];
    int tid = threadIdx.x;
    float2 w1s1, w1s2; stage_twiddles(tid, w1s1, w1s2);
    int f = tid >> 6, l = tid & 63;
    size_t base = (size_t)blockIdx.y * M_FFT + (size_t)blockIdx.x * 4096;
    int lin0 = blockIdx.x * 4096;
    float2* g = data + base;
    const float4* g4 = (const float4*)g;
    const float2* ks = kspec + lin0 + f*512;
    float2* sp = sh + f * SD;

    #pragma unroll
    for (int it = 0; it < 4; it++){
        int idx = it*512 + tid;
        float4 v = g4[idx];
        int e = (idx*2) & 511;
        int row = idx >> 8;
        float2* rp = sh + row*SD;
        rp[SWZ(e)]     = make_float2(v.x, v.y);
        rp[SWZ(e + 1)] = make_float2(v.z, v.w);
    }
    __syncthreads();

    float2 u[8];
    fft512_reg<-1>(sh, tid, w1s1, w1s2, u);   // u[q] = elem (l+64q) of row f

    // spectral multiply in registers (coalesced 256B warp reads)
    #pragma unroll
    for (int q = 0; q < 8; q++) u[q] = cmul(u[q], ks[l + 64*q]);

    __syncthreads();                           // stage-2 reads done; reuse sh
    #pragma unroll
    for (int q = 0; q < 8; q++) sp[SWZ(l + 64*q)] = u[q];
    __syncthreads();

    fft512_reg<+1>(sh, tid, w1s1, w1s2, u);

    const float s = 1.0f / 512.0f;
    float2* gr = g + f*512;
    #pragma unroll
    for (int q = 0; q < 8; q++){
        float2 v = u[q];
        gr[l + 64*q] = make_float2(v.x * s, v.y * s);
    }
}

// Inverse passA + H-spectrum extraction (writes only the KBINS slab).
__global__ void __launch_bounds__(512) pA_inv_H(const float2* __restrict__ in,
                                                float2* __restrict__ HS){
    __shared__ float2 sh[8 * SD];
    int tid = threadIdx.x;
    float2 w1s1, w1s2; stage_twiddles(tid, w1s1, w1s2);
    int p = blockIdx.y;
    int c0 = blockIdx.x * 8;
    int cc = tid & 7, rt = tid >> 3, c = c0 + cc;
    const float2* gin = in + (size_t)p * M_FFT;
    {
        float2 tw, ws; fourstep_init(rt, c, +1.f, tw, ws);
        #pragma unroll
        for (int it = 0; it < 8; it++){
            int r = it*64 + rt;
            sh[cc*SD + SWZ(r)] = cmul(gin[r*512 + c], tw);
            tw = cmul(tw, ws);
        }
    }
    __syncthreads();
    fft512_block<+1>(sh, tid, w1s1, w1s2);
    const float s = 1.0f / 512.0f;
    #pragma unroll
    for (int it = 0; it < 8; it++){
        int r = it*64 + rt;
        int k = r*512 + c;
        if (k < KBINS){
            float2 v = sh[cc*SD + SWZ(r)];
            v.x *= s; v.y *= s;
            HS[(size_t)p * KBINS + k] = cmul(g_T1[k], v);
        }
    }
}

// CZT-X inverse passA + (Y = X*H, chirps, DC/Nyquist fix) + CZT-3 forward passA.
__global__ void __launch_bounds__(512) fused_inv_d_fwd(float2* __restrict__ data,
                                                       const float2* __restrict__ HS){
    __shared__ float2 sh[8 * SD];
    int tid = threadIdx.x;
    float2 w1s1, w1s2; stage_twiddles(tid, w1s1, w1s2);
    int p = blockIdx.y;
    int c0 = blockIdx.x * 8;
    int cc = tid & 7, rt = tid >> 3, c = c0 + cc;
    float2* g = data + (size_t)p * M_FFT;
    {
        float2 tw, ws; fourstep_init(rt, c, +1.f, tw, ws);
        #pragma unroll
        for (int it = 0; it < 8; it++){
            int r = it*64 + rt;
            sh[cc*SD + SWZ(r)] = cmul(g[r*512 + c], tw);
            tw = cmul(tw, ws);
        }
    }
    __syncthreads();
    fft512_block<+1>(sh, tid, w1s1, w1s2);
    const float s = 1.0f / 512.0f;
    #pragma unroll
    for (int it = 0; it < 8; it++){
        int r = it*64 + rt;
        int k = r*512 + c;
        float2 d = make_float2(0.f, 0.f);
        if (k < KBINS){
            float2 a = sh[cc*SD + SWZ(r)];
            a.x *= s; a.y *= s;
            float2 X = cmul(g_T1[k], a);
            float2 Y = cmul(X, HS[(size_t)p * KBINS + k]);
            if (k == 0 || k == KBINS - 1) Y = make_float2(0.5f * Y.x, 0.f);
            d = cmul(Y, g_T2[k]);
        }
        sh[cc*SD + SWZ(r)] = d;   // own slot
    }
    __syncthreads();
    fft512_block<-1>(sh, tid, w1s1, w1s2);
    float2 tw, ws; fourstep_init(rt, c, -1.f, tw, ws);
    #pragma unroll
    for (int it = 0; it < 8; it++){
        int r = it*64 + rt;
        g[r*512 + c] = cmul(sh[cc*SD + SWZ(r)], tw);
        tw = cmul(tw, ws);
    }
}

// Inverse passA + final real output (writes only the LX real samples).
__global__ void __launch_bounds__(512) pA_inv_out(const float2* __restrict__ in,
                                                  float* __restrict__ out){
    __shared__ float2 sh[8 * SD];
    int tid = threadIdx.x;
    float2 w1s1, w1s2; stage_twiddles(tid, w1s1, w1s2);
    int p = blockIdx.y;
    int c0 = blockIdx.x * 8;
    int cc = tid & 7, rt = tid >> 3, c = c0 + cc;
    const float2* gin = in + (size_t)p * M_FFT;
    {
        float2 tw, ws; fourstep_init(rt, c, +1.f, tw, ws);
        #pragma unroll
        for (int it = 0; it < 8; it++){
            int r = it*64 + rt;
            sh[cc*SD + SWZ(r)] = cmul(gin[r*512 + c], tw);
            tw = cmul(tw, ws);
        }
    }
    __syncthreads();
    fft512_block<+1>(sh, tid, w1s1, w1s2);
    const float sc = (2.0f / (float)N2C) * (1.0f / 512.0f);
    #pragma unroll
    for (int it = 0; it < 8; it++){
        int r = it*64 + rt;
        int n = r*512 + c;
        if (n < LX){
            float2 v = sh[cc*SD + SWZ(r)];
            float2 T = g_T2[n];
            out[(size_t)p * LX + n] = sc * (T.x * v.x - T.y * v.y);
        }
    }
}

// ------------------------- launch -------------------------------------------
extern "C" void kernel_launch(void* const* d_in, const int* in_sizes, int n_in,
                              void* d_out, int out_size){
    (void)in_sizes; (void)n_in; (void)out_size;
    const float* x = (const float*)d_in[0];
    const float* h = (const float*)d_in[1];
    float* out = (float*)d_out;

    float2 *bufA, *hs, *kern, *kspec;
    cudaGetSymbolAddress((void**)&bufA, g_bufA);
    cudaGetSymbolAddress((void**)&hs,   g_HS);
    cudaGetSymbolAddress((void**)&kern, g_kern);
    cudaGetSymbolAddress((void**)&kspec,g_kspec);

    const dim3 fgrid(64, NPAIR);
    const dim3 kgrid(64, 2);

    // 0. tables + chirp kernels + their spectra
    init_tables<<<512, 256>>>();
    build_kern<<<M_FFT / 256, 256>>>();
    passA_small<<<kgrid, 512>>>(kern, kspec);
    passB_small<<<kgrid, 512>>>(kspec);

    // 1. H path: CZT of h on the N1 grid -> g_HS
    pA_fwd_input<LH><<<fgrid, 512>>>(bufA, h);
    fusedB_conv<<<fgrid, 512>>>(bufA, kspec);            // * B1
    pA_inv_H<<<fgrid, 512>>>(bufA, hs);

    // 2. X path forward CZT
    pA_fwd_input<LX><<<fgrid, 512>>>(bufA, x);
    fusedB_conv<<<fgrid, 512>>>(bufA, kspec);            // * B1

    // 3. inverse passA -> Y=X*H pointwise -> forward passA of synthesis CZT
    fused_inv_d_fwd<<<fgrid, 512>>>(bufA, hs);
    fusedB_conv<<<fgrid, 512>>>(bufA, kspec + M_FFT);    // * B2

    // 4. inverse passA + final real output
    pA_inv_out<<<fgrid, 512>>>(bufA, out);
}

// round 6
// speedup vs baseline: 2.2769x; 1.0994x over previous
#include <cuda_runtime.h>
#include <math.h>

// ---------------------------------------------------------------------------
// Causal FFT convolution matching:
//   X = rfft(x, n=163839); H = rfft(h, n=163839); Y = X*H
//   y = irfft(Y)   (default n = 163838 <-- mismatched grids), out = y[:131072]
//
// R6 pipeline (z-squaring trick removes the separate H path):
//   z = x + i*h  (both real, support LX)
//   Z = FFT_2^18(z);  Z -> Z^2  (pointwise, scramble-safe)
//   w = Im(IFFT(Z^2))/2 = linear conv(x,h), length N1 = LX+LH-1 exactly
//   Y_k = DFT_N1(w)[k], k<81920  via Bluestein CZT (x B1)
//   y   = irfft_N2(Y) via Bluestein CZT (x B2), first LX samples
// All FFTs: four-step 512x512 on 2^18, swizzled shared, computed twiddles.
// 256-thread blocks (4 sub-FFTs), 6 blocks/SM for latency hiding.
// ---------------------------------------------------------------------------

#define M_FFT  262144
#define NPAIR  128
#define LX     131072
#define LH     32768
#define KBINS  81920
#define N1C    163839
#define N2C    163838
#define SD     516

__device__ __align__(16) float2 g_bufA[(size_t)NPAIR * M_FFT];   // 268 MB
__device__ __align__(16) float2 g_T1 [N1C];     // exp(-i pi n^2 / N1)
__device__ __align__(16) float2 g_T2 [LX];      // exp(+i pi n^2 / N2)
__device__ __align__(16) float2 g_kern [2 * M_FFT];
__device__ __align__(16) float2 g_kspec[2 * M_FFT];

__device__ __forceinline__ int SWZ(int m){ return m ^ ((m >> 4) & 15); }

// ------------------------- complex helpers ---------------------------------
__device__ __forceinline__ float2 cadd(float2 a, float2 b){ return make_float2(a.x+b.x, a.y+b.y); }
__device__ __forceinline__ float2 csub(float2 a, float2 b){ return make_float2(a.x-b.x, a.y-b.y); }
__device__ __forceinline__ float2 cconj(float2 a){ return make_float2(a.x, -a.y); }
__device__ __forceinline__ float2 cmul(float2 a, float2 b){
    return make_float2(a.x*b.x - a.y*b.y, a.x*b.y + a.y*b.x);
}
template<int SIGN> __device__ __forceinline__ float2 mul_i(float2 a){
    return (SIGN < 0) ? make_float2(a.y, -a.x) : make_float2(-a.y, a.x);
}

template<int SIGN>
__device__ __forceinline__ void fft4(float2 &x0, float2 &x1, float2 &x2, float2 &x3){
    float2 t0 = cadd(x0, x2), t1 = csub(x0, x2);
    float2 t2 = cadd(x1, x3), t3 = csub(x1, x3);
    float2 t3r = mul_i<SIGN>(t3);
    x0 = cadd(t0, t2);
    x2 = csub(t0, t2);
    x1 = cadd(t1, t3r);
    x3 = csub(t1, t3r);
}

template<int SIGN>
__device__ __forceinline__ void fft8(float2 u[8]){
    float2 e0=u[0], e1=u[2], e2=u[4], e3=u[6];
    float2 o0=u[1], o1=u[3], o2=u[5], o3=u[7];
    fft4<SIGN>(e0,e1,e2,e3);
    fft4<SIGN>(o0,o1,o2,o3);
    const float s2 = 0.70710678118654752440f;
    float2 w1 = make_float2( s2, SIGN * s2);
    float2 w3 = make_float2(-s2, SIGN * s2);
    o1 = cmul(o1, w1);
    o2 = mul_i<SIGN>(o2);
    o3 = cmul(o3, w3);
    u[0]=cadd(e0,o0); u[4]=csub(e0,o0);
    u[1]=cadd(e1,o1); u[5]=csub(e1,o1);
    u[2]=cadd(e2,o2); u[6]=csub(e2,o2);
    u[3]=cadd(e3,o3); u[7]=csub(e3,o3);
}

// Hoisted per-thread stage twiddles (forward sign).
__device__ __forceinline__ void stage_twiddles(int tid, float2 &w1s1, float2 &w1s2){
    float sn, cs;
    sincospif((float)(tid & 7) * (1.0f/32.0f), &sn, &cs);
    w1s1 = make_float2(cs, -sn);
    sincospif((float)(tid & 63) * (1.0f/256.0f), &sn, &cs);
    w1s2 = make_float2(cs, -sn);
}

// Stages 0+1 of the 512-pt FFT (shared in, shared out). Internal syncs.
template<int SIGN>
__device__ __forceinline__ void fft512_s01(float2* sp, int l, float2 w1f_s1){
    float2 u[8];
    { // stage 0: digit-reversed gather, radix-8
        #pragma unroll
        for (int q = 0; q < 8; q++){
            int src = q*64 + (l & 7)*8 + (l >> 3);
            u[q] = sp[SWZ(src)];
        }
        fft8<SIGN>(u);
        __syncthreads();
        #pragma unroll
        for (int r = 0; r < 8; r++) sp[SWZ(l*8 + r)] = u[r];
    }
    __syncthreads();
    { // stage 1 (m=64)
        int gg = l >> 3, j = l & 7;
        int base = gg*64 + j;
        #pragma unroll
        for (int q = 0; q < 8; q++) u[q] = sp[SWZ(base + q*8)];
        float2 w1 = (SIGN < 0) ? w1f_s1 : cconj(w1f_s1);
        float2 w = w1;
        #pragma unroll
        for (int q = 1; q < 8; q++){ u[q] = cmul(u[q], w); w = cmul(w, w1); }
        fft8<SIGN>(u);
        #pragma unroll
        for (int r = 0; r < 8; r++) sp[SWZ(base + r*8)] = u[r];
    }
    __syncthreads();
}

// Full FFT-512, shared in / shared out. 4 sub-FFTs per 256-thread block.
template<int SIGN>
__device__ void fft512_block(float2* s, int tid, float2 w1f_s1, float2 w1f_s2){
    int f = tid >> 6, l = tid & 63;
    float2* sp = s + f * SD;
    fft512_s01<SIGN>(sp, l, w1f_s1);
    float2 u[8];
    { // stage 2 (m=512)
        int j = l;
        #pragma unroll
        for (int q = 0; q < 8; q++) u[q] = sp[SWZ(j + q*64)];
        float2 w1 = (SIGN < 0) ? w1f_s2 : cconj(w1f_s2);
        float2 w = w1;
        #pragma unroll
        for (int q = 1; q < 8; q++){ u[q] = cmul(u[q], w); w = cmul(w, w1); }
        fft8<SIGN>(u);
        #pragma unroll
        for (int r = 0; r < 8; r++) sp[SWZ(j + r*64)] = u[r];
    }
    __syncthreads();
}

// Full FFT-512, shared in / REGISTER out (u[q] = elem l+64q of sub-FFT f).
// Caller must __syncthreads() before reusing the shared tile.
template<int SIGN>
__device__ void fft512_reg(float2* s, int tid, float2 w1f_s1, float2 w1f_s2,
                           float2 u[8]){
    int f = tid >> 6, l = tid & 63;
    float2* sp = s + f * SD;
    fft512_s01<SIGN>(sp, l, w1f_s1);
    int j = l;
    #pragma unroll
    for (int q = 0; q < 8; q++) u[q] = sp[SWZ(j + q*64)];
    float2 w1 = (SIGN < 0) ? w1f_s2 : cconj(w1f_s2);
    float2 w = w1;
    #pragma unroll
    for (int q = 1; q < 8; q++){ u[q] = cmul(u[q], w); w = cmul(w, w1); }
    fft8<SIGN>(u);
}

// ------------------------- table / kernel construction ---------------------
__global__ void init_tables(){
    int i = blockIdx.x * blockDim.x + threadIdx.x;
    if (i < N1C){
        unsigned long long ii = (unsigned long long)i * (unsigned long long)i;
        double s, c;
        double a1 = (double)(ii % (2ULL * N1C)) / (double)N1C;
        sincospi(a1, &s, &c);
        g_T1[i] = make_float2((float)c, (float)(-s));
    }
    if (i < LX){
        unsigned long long ii = (unsigned long long)i * (unsigned long long)i;
        double s, c;
        double a2 = (double)(ii % (2ULL * N2C)) / (double)N2C;
        sincospi(a2, &s, &c);
        g_T2[i] = make_float2((float)c, (float)s);
    }
}

__global__ void build_kern(){
    int i = blockIdx.x * blockDim.x + threadIdx.x;
    if (i >= M_FFT) return;
    // b1[j] = conj(T1[|j|]), j in [-(N1C-1), KBINS-1]  (input length N1C now)
    float2 v = make_float2(0.f, 0.f);
    if (i <= KBINS - 1)               { float2 t = g_T1[i];          v = make_float2(t.x, -t.y); }
    else if (i >= M_FFT - (N1C - 1))  { float2 t = g_T1[M_FFT - i];  v = make_float2(t.x, -t.y); }
    g_kern[i] = v;
    // b2[j] = conj(T2[|j|]), j in [-(KBINS-1), LX-1]
    float2 w = make_float2(0.f, 0.f);
    if (i <= LX - 1)                  { float2 t = g_T2[i];          w = make_float2(t.x, -t.y); }
    else if (i >= M_FFT - (KBINS-1))  { float2 t = g_T2[M_FFT - i];  w = make_float2(t.x, -t.y); }
    g_kern[M_FFT + i] = w;
}

// Four-step twiddle recurrence: tw = exp(sgn*2pi*i*r0*c/2^18), step for r += 64.
__device__ __forceinline__ void fourstep_init(int r0, int c, float sgn,
                                              float2 &tw, float2 &ws){
    float sa, ca, sb, cb;
    sincospif((float)(r0 * c) * (1.0f/131072.0f), &sa, &ca);
    sincospif((float)c * (1.0f/2048.0f), &sb, &cb);
    tw = make_float2(ca, sgn * sa);
    ws = make_float2(cb, sgn * sb);
}

// --- small passes for the chirp-kernel spectra (batch 2) --------------------
__global__ void __launch_bounds__(256, 6) passA_small(const float2* __restrict__ in,
                                                      float2* __restrict__ out){
    __shared__ float2 sh[4 * SD];
    int tid = threadIdx.x;
    float2 w1s1, w1s2; stage_twiddles(tid, w1s1, w1s2);
    size_t base = (size_t)blockIdx.y * M_FFT;
    int c0 = blockIdx.x * 4;
    int cc = tid & 3, rt = tid >> 2, c = c0 + cc;
    const float2* gin = in + base;
    #pragma unroll
    for (int it = 0; it < 8; it++){
        int r = it*64 + rt;
        sh[cc*SD + SWZ(r)] = gin[r*512 + c];
    }
    __syncthreads();
    fft512_block<-1>(sh, tid, w1s1, w1s2);
    float2 tw, ws; fourstep_init(rt, c, -1.f, tw, ws);
    float2* gout = out + base;
    #pragma unroll
    for (int it = 0; it < 8; it++){
        int r = it*64 + rt;
        gout[r*512 + c] = cmul(sh[cc*SD + SWZ(r)], tw);
        tw = cmul(tw, ws);
    }
}

__global__ void __launch_bounds__(256, 6) passB_small(float2* __restrict__ data){
    __shared__ float2 sh[4 * SD];
    int tid = threadIdx.x;
    float2 w1s1, w1s2; stage_twiddles(tid, w1s1, w1s2);
    size_t base = (size_t)blockIdx.y * M_FFT + (size_t)blockIdx.x * 2048;
    float2* g = data + base;
    #pragma unroll
    for (int it = 0; it < 8; it++){
        int idx = it*256 + tid;
        sh[(idx >> 9)*SD + SWZ(idx & 511)] = g[idx];
    }
    __syncthreads();
    fft512_block<-1>(sh, tid, w1s1, w1s2);
    #pragma unroll
    for (int it = 0; it < 8; it++){
        int idx = it*256 + tid;
        g[idx] = sh[(idx >> 9)*SD + SWZ(idx & 511)];
    }
}

// ------------------- fused data-path kernels --------------------------------

// K1: forward passA of z = x + i*h (zero-padded), no chirp.
__global__ void __launch_bounds__(256, 6) pA_fwd_z(float2* __restrict__ out,
                                                   const float* __restrict__ x,
                                                   const float* __restrict__ h){
    __shared__ float2 sh[4 * SD];
    int tid = threadIdx.x;
    float2 w1s1, w1s2; stage_twiddles(tid, w1s1, w1s2);
    int p = blockIdx.y;
    int c0 = blockIdx.x * 4;
    int cc = tid & 3, rt = tid >> 2, c = c0 + cc;
    const float* gx = x + (size_t)p * LX;
    const float* gh = h + (size_t)p * LH;
    #pragma unroll
    for (int it = 0; it < 8; it++){
        int r = it*64 + rt;
        int n = r*512 + c;
        float2 v = make_float2(0.f, 0.f);
        if (n < LX) v.x = gx[n];
        if (n < LH) v.y = gh[n];
        sh[cc*SD + SWZ(r)] = v;
    }
    __syncthreads();
    fft512_block<-1>(sh, tid, w1s1, w1s2);
    float2 tw, ws; fourstep_init(rt, c, -1.f, tw, ws);
    float2* gout = out + (size_t)p * M_FFT;
    #pragma unroll
    for (int it = 0; it < 8; it++){
        int r = it*64 + rt;
        gout[r*512 + c] = cmul(sh[cc*SD + SWZ(r)], tw);
        tw = cmul(tw, ws);
    }
}

// K2: passB fwd -> Z^2 in registers -> passB inv (in place).
__global__ void __launch_bounds__(256, 6) fusedB_sq(float2* __restrict__ data){
    __shared__ float2 sh[4 * SD];
    int tid = threadIdx.x;
    float2 w1s1, w1s2; stage_twiddles(tid, w1s1, w1s2);
    int f = tid >> 6, l = tid & 63;
    size_t base = (size_t)blockIdx.y * M_FFT + (size_t)blockIdx.x * 2048;
    float2* g = data + base;
    const float4* g4 = (const float4*)g;
    float2* sp = sh + f * SD;

    #pragma unroll
    for (int it = 0; it < 4; it++){
        int idx = it*256 + tid;
        float4 v = g4[idx];
        int e = (idx*2) & 511;
        float2* rp = sh + (idx >> 8)*SD;
        rp[SWZ(e)]     = make_float2(v.x, v.y);
        rp[SWZ(e + 1)] = make_float2(v.z, v.w);
    }
    __syncthreads();

    float2 u[8];
    fft512_reg<-1>(sh, tid, w1s1, w1s2, u);
    #pragma unroll
    for (int q = 0; q < 8; q++) u[q] = cmul(u[q], u[q]);   // Z^2
    __syncthreads();
    #pragma unroll
    for (int q = 0; q < 8; q++) sp[SWZ(l + 64*q)] = u[q];
    __syncthreads();
    fft512_reg<+1>(sh, tid, w1s1, w1s2, u);

    const float s = 1.0f / 512.0f;
    float2* gr = g + f*512;
    #pragma unroll
    for (int q = 0; q < 8; q++){
        float2 v = u[q];
        gr[l + 64*q] = make_float2(v.x * s, v.y * s);
    }
}

// K4/K6: passB fwd * kspec * passB inv (in place).
__global__ void __launch_bounds__(256, 6) fusedB_conv(float2* __restrict__ data,
                                                      const float2* __restrict__ kspec){
    __shared__ float2 sh[4 * SD];
    int tid = threadIdx.x;
    float2 w1s1, w1s2; stage_twiddles(tid, w1s1, w1s2);
    int f = tid >> 6, l = tid & 63;
    size_t base = (size_t)blockIdx.y * M_FFT + (size_t)blockIdx.x * 2048;
    int lin0 = blockIdx.x * 2048;
    float2* g = data + base;
    const float4* g4 = (const float4*)g;
    const float2* ks = kspec + lin0 + f*512;
    float2* sp = sh + f * SD;

    #pragma unroll
    for (int it = 0; it < 4; it++){
        int idx = it*256 + tid;
        float4 v = g4[idx];
        int e = (idx*2) & 511;
        float2* rp = sh + (idx >> 8)*SD;
        rp[SWZ(e)]     = make_float2(v.x, v.y);
        rp[SWZ(e + 1)] = make_float2(v.z, v.w);
    }
    __syncthreads();

    float2 u[8];
    fft512_reg<-1>(sh, tid, w1s1, w1s2, u);
    #pragma unroll
    for (int q = 0; q < 8; q++) u[q] = cmul(u[q], ks[l + 64*q]);
    __syncthreads();
    #pragma unroll
    for (int q = 0; q < 8; q++) sp[SWZ(l + 64*q)] = u[q];
    __syncthreads();
    fft512_reg<+1>(sh, tid, w1s1, w1s2, u);

    const float s = 1.0f / 512.0f;
    float2* gr = g + f*512;
    #pragma unroll
    for (int q = 0; q < 8; q++){
        float2 v = u[q];
        gr[l + 64*q] = make_float2(v.x * s, v.y * s);
    }
}

// K3: inverse passA (finishes IFFT of Z^2) -> w = Im/2 -> a_n = w*T1[n] -> fwd passA.
__global__ void __launch_bounds__(256, 6) fused_inv_w_fwd(float2* __restrict__ data){
    __shared__ float2 sh[4 * SD];
    int tid = threadIdx.x;
    float2 w1s1, w1s2; stage_twiddles(tid, w1s1, w1s2);
    int p = blockIdx.y;
    int c0 = blockIdx.x * 4;
    int cc = tid & 3, rt = tid >> 2, c = c0 + cc;
    float2* g = data + (size_t)p * M_FFT;
    {
        float2 tw, ws; fourstep_init(rt, c, +1.f, tw, ws);
        #pragma unroll
        for (int it = 0; it < 8; it++){
            int r = it*64 + rt;
            sh[cc*SD + SWZ(r)] = cmul(g[r*512 + c], tw);
            tw = cmul(tw, ws);
        }
    }
    __syncthreads();
    fft512_block<+1>(sh, tid, w1s1, w1s2);
    const float s = 0.5f / 512.0f;           // 1/512 IFFT scale * Im/2
    #pragma unroll
    for (int it = 0; it < 8; it++){
        int r = it*64 + rt;
        int n = r*512 + c;
        float2 d = make_float2(0.f, 0.f);
        if (n < N1C){
            float wv = sh[cc*SD + SWZ(r)].y * s;   // w_n = Im(conv(z,z))/2
            float2 t = g_T1[n];
            d = make_float2(wv * t.x, wv * t.y);
        }
        sh[cc*SD + SWZ(r)] = d;
    }
    __syncthreads();
    fft512_block<-1>(sh, tid, w1s1, w1s2);
    float2 tw, ws; fourstep_init(rt, c, -1.f, tw, ws);
    #pragma unroll
    for (int it = 0; it < 8; it++){
        int r = it*64 + rt;
        g[r*512 + c] = cmul(sh[cc*SD + SWZ(r)], tw);
        tw = cmul(tw, ws);
    }
}

// K5: inverse passA (finishes CZT1 conv) -> Y_k = T1[k]*s_k, DC/Nyq fix,
//     d_k = Y_k*T2[k] -> forward passA of synthesis CZT.
__global__ void __launch_bounds__(256, 6) fused_inv_spec_fwd(float2* __restrict__ data){
    __shared__ float2 sh[4 * SD];
    int tid = threadIdx.x;
    float2 w1s1, w1s2; stage_twiddles(tid, w1s1, w1s2);
    int p = blockIdx.y;
    int c0 = blockIdx.x * 4;
    int cc = tid & 3, rt = tid >> 2, c = c0 + cc;
    float2* g = data + (size_t)p * M_FFT;
    {
        float2 tw, ws; fourstep_init(rt, c, +1.f, tw, ws);
        #pragma unroll
        for (int it = 0; it < 8; it++){
            int r = it*64 + rt;
            sh[cc*SD + SWZ(r)] = cmul(g[r*512 + c], tw);
            tw = cmul(tw, ws);
        }
    }
    __syncthreads();
    fft512_block<+1>(sh, tid, w1s1, w1s2);
    const float s = 1.0f / 512.0f;
    #pragma unroll
    for (int it = 0; it < 8; it++){
        int r = it*64 + rt;
        int k = r*512 + c;
        float2 d = make_float2(0.f, 0.f);
        if (k < KBINS){
            float2 a = sh[cc*SD + SWZ(r)];
            a.x *= s; a.y *= s;
            float2 Y = cmul(g_T1[k], a);          // Y_k = DFT_N1(w)[k] = X_k*H_k
            if (k == 0 || k == KBINS - 1) Y = make_float2(0.5f * Y.x, 0.f);
            d = cmul(Y, g_T2[k]);
        }
        sh[cc*SD + SWZ(r)] = d;
    }
    __syncthreads();
    fft512_block<-1>(sh, tid, w1s1, w1s2);
    float2 tw, ws; fourstep_init(rt, c, -1.f, tw, ws);
    #pragma unroll
    for (int it = 0; it < 8; it++){
        int r = it*64 + rt;
        g[r*512 + c] = cmul(sh[cc*SD + SWZ(r)], tw);
        tw = cmul(tw, ws);
    }
}

// K7: inverse passA + final real output.
__global__ void __launch_bounds__(256, 6) pA_inv_out(const float2* __restrict__ in,
                                                     float* __restrict__ out){
    __shared__ float2 sh[4 * SD];
    int tid = threadIdx.x;
    float2 w1s1, w1s2; stage_twiddles(tid, w1s1, w1s2);
    int p = blockIdx.y;
    int c0 = blockIdx.x * 4;
    int cc = tid & 3, rt = tid >> 2, c = c0 + cc;
    const float2* gin = in + (size_t)p * M_FFT;
    {
        float2 tw, ws; fourstep_init(rt, c, +1.f, tw, ws);
        #pragma unroll
        for (int it = 0; it < 8; it++){
            int r = it*64 + rt;
            sh[cc*SD + SWZ(r)] = cmul(gin[r*512 + c], tw);
            tw = cmul(tw, ws);
        }
    }
    __syncthreads();
    fft512_block<+1>(sh, tid, w1s1, w1s2);
    const float sc = (2.0f / (float)N2C) * (1.0f / 512.0f);
    #pragma unroll
    for (int it = 0; it < 8; it++){
        int r = it*64 + rt;
        int n = r*512 + c;
        if (n < LX){
            float2 v = sh[cc*SD + SWZ(r)];
            float2 T = g_T2[n];
            out[(size_t)p * LX + n] = sc * (T.x * v.x - T.y * v.y);
        }
    }
}

// ------------------------- launch -------------------------------------------
extern "C" void kernel_launch(void* const* d_in, const int* in_sizes, int n_in,
                              void* d_out, int out_size){
    (void)in_sizes; (void)n_in; (void)out_size;
    const float* x = (const float*)d_in[0];
    const float* h = (const float*)d_in[1];
    float* out = (float*)d_out;

    float2 *bufA, *kern, *kspec;
    cudaGetSymbolAddress((void**)&bufA, g_bufA);
    cudaGetSymbolAddress((void**)&kern, g_kern);
    cudaGetSymbolAddress((void**)&kspec,g_kspec);

    const dim3 fgrid(128, NPAIR);
    const dim3 kgrid(128, 2);

    // 0. tables + chirp kernels + their spectra
    init_tables<<<(N1C + 255) / 256, 256>>>();
    build_kern<<<M_FFT / 256, 256>>>();
    passA_small<<<kgrid, 256>>>(kern, kspec);
    passB_small<<<kgrid, 256>>>(kspec);

    // 1-2. Z = FFT(x + i h); Z^2; back to time: conv(z,z)
    pA_fwd_z<<<fgrid, 256>>>(bufA, x, h);
    fusedB_sq<<<fgrid, 256>>>(bufA);

    // 3-4. w = Im/2, chirp, CZT-1 convolution (x B1)
    fused_inv_w_fwd<<<fgrid, 256>>>(bufA);
    fusedB_conv<<<fgrid, 256>>>(bufA, kspec);

    // 5-6. Y_k = T1[k]*s_k, irfft prep, chirp2, CZT-2 convolution (x B2)
    fused_inv_spec_fwd<<<fgrid, 256>>>(bufA);
    fusedB_conv<<<fgrid, 256>>>(bufA, kspec + M_FFT);

    // 7. final inverse passA + real output
    pA_inv_out<<<fgrid, 256>>>(bufA, out);
}